// round 7
// baseline (speedup 1.0000x reference)
#include <cuda_runtime.h>
#include <cuda_bf16.h>
#include <math.h>
#include <cstdint>

// Problem constants
#define D      256
#define NH     8
#define HD     32
#define NE     5
#define LQ     100
#define LK     1024
#define BB     16
#define MQ     (LQ*BB)      // 1600
#define MK     (LK*BB)      // 16384
#define NEXP   (NE*D)       // 1280
#define KCAT   768          // W cat: [hi|hi|lo]
#define KA     512          // A cat: [hi|lo] (hi chunks re-read for 3rd term)
#define NCHUNK 12

// ---------------- scratch (device globals) ---------------------------------
__device__ float g_Q[MQ*NEXP];
__device__ float g_KV[2L*MK*NEXP];          // [0]=K, [1]=V
__device__ float g_gate[MQ*NE];
__device__ float g_ctx[NE*MQ*D];
__device__ float g_out[NE*MQ*D];

__device__ __nv_bfloat16 g_Aq[MQ*KA];
__device__ __nv_bfloat16 g_Akv[2L*MK*KA];   // [0]=K-act, [1]=V-act
__device__ __nv_bfloat16 g_Ac[NE*MQ*KA];
__device__ __nv_bfloat16 g_Wq[NEXP*KCAT];
__device__ __nv_bfloat16 g_Wkv[2L*NEXP*KCAT]; // [0]=Wk, [1]=Wv
__device__ __nv_bfloat16 g_Wo[NEXP*KCAT];

// ---------------- helpers ----------------------------------------------------
__device__ __forceinline__ uint32_t smem_u32(const void* p) {
    uint32_t a;
    asm("{ .reg .u64 t; cvta.to.shared.u64 t, %1; cvt.u32.u64 %0, t; }"
        : "=r"(a) : "l"(p));
    return a;
}

__device__ __forceinline__ uint32_t sw(uint32_t off) {
    return off ^ ((off >> 3) & 0x70);
}

__device__ __forceinline__ void cp16(uint32_t dst, const void* src, bool pred) {
    int sz = pred ? 16 : 0;
    asm volatile("cp.async.cg.shared.global [%0], [%1], 16, %2;"
                 :: "r"(dst), "l"(src), "r"(sz));
}
#define CP_COMMIT() asm volatile("cp.async.commit_group;" ::: "memory")
#define CP_WAIT2()  asm volatile("cp.async.wait_group 2;" ::: "memory")
#define CP_WAIT1()  asm volatile("cp.async.wait_group 1;" ::: "memory")
#define CP_WAIT0()  asm volatile("cp.async.wait_group 0;" ::: "memory")

__device__ __forceinline__ void ldsm_x4(uint32_t* r, uint32_t addr) {
    asm volatile("ldmatrix.sync.aligned.m8n8.x4.shared.b16 {%0,%1,%2,%3}, [%4];"
                 : "=r"(r[0]), "=r"(r[1]), "=r"(r[2]), "=r"(r[3]) : "r"(addr));
}

__device__ __forceinline__ void ldsm_x4_t(uint32_t* r, uint32_t addr) {
    asm volatile("ldmatrix.sync.aligned.m8n8.x4.trans.shared.b16 {%0,%1,%2,%3}, [%4];"
                 : "=r"(r[0]), "=r"(r[1]), "=r"(r[2]), "=r"(r[3]) : "r"(addr));
}

__device__ __forceinline__ void mma16816(float* d, const uint32_t* a,
                                         const uint32_t* b) {
    asm volatile(
        "mma.sync.aligned.m16n8k16.row.col.f32.bf16.bf16.f32 "
        "{%0,%1,%2,%3}, {%4,%5,%6,%7}, {%8,%9}, {%0,%1,%2,%3};"
        : "+f"(d[0]), "+f"(d[1]), "+f"(d[2]), "+f"(d[3])
        : "r"(a[0]), "r"(a[1]), "r"(a[2]), "r"(a[3]), "r"(b[0]), "r"(b[1]));
}

__device__ __forceinline__ uint32_t packbf2(float x, float y) {
    uint32_t d;
    asm("cvt.rn.bf16x2.f32 %0, %1, %2;" : "=r"(d) : "f"(y), "f"(x));
    return d;
}

__device__ __forceinline__ void split2(float x, float y, uint32_t& hi, uint32_t& lo) {
    hi = packbf2(x, y);
    __nv_bfloat162 h = *(__nv_bfloat162*)&hi;
    lo = packbf2(x - __bfloat162float(h.x), y - __bfloat162float(h.y));
}

// ---------------- split-bf16 conversions (vectorized) -----------------------
// A row layout: [hi(256) | lo(256)]
__global__ void convert_act(const float* __restrict__ a,
                            const float* __restrict__ b,
                            __nv_bfloat16* __restrict__ out, int M) {
    int idx = blockIdx.x * blockDim.x + threadIdx.x;   // over M*64 float4s
    if (idx >= M * 64) return;
    int m = idx >> 6, k4 = (idx & 63) << 2;
    float4 f = *(const float4*)(a + (long)idx * 4);
    if (b) {
        float4 g = *(const float4*)(b + (long)idx * 4);
        f.x += g.x; f.y += g.y; f.z += g.z; f.w += g.w;
    }
    uint32_t h01, l01, h23, l23;
    split2(f.x, f.y, h01, l01);
    split2(f.z, f.w, h23, l23);
    long base = (long)m * KA + k4;
    *(uint2*)(out + base)       = make_uint2(h01, h23);
    *(uint2*)(out + base + 256) = make_uint2(l01, l23);
}

// fused K/V conversion: reads memory (+pos) once
__global__ void convert_kv(const float* __restrict__ mem,
                           const float* __restrict__ pos,
                           __nv_bfloat16* __restrict__ outK,
                           __nv_bfloat16* __restrict__ outV) {
    int idx = blockIdx.x * blockDim.x + threadIdx.x;
    if (idx >= MK * 64) return;
    int m = idx >> 6, k4 = (idx & 63) << 2;
    float4 v = *(const float4*)(mem + (long)idx * 4);
    float4 p = *(const float4*)(pos + (long)idx * 4);
    long base = (long)m * KA + k4;
    uint32_t h01, l01, h23, l23;
    split2(v.x + p.x, v.y + p.y, h01, l01);
    split2(v.z + p.z, v.w + p.w, h23, l23);
    *(uint2*)(outK + base)       = make_uint2(h01, h23);
    *(uint2*)(outK + base + 256) = make_uint2(l01, l23);
    split2(v.x, v.y, h01, l01);
    split2(v.z, v.w, h23, l23);
    *(uint2*)(outV + base)       = make_uint2(h01, h23);
    *(uint2*)(outV + base + 256) = make_uint2(l01, l23);
}

// all four weight tensors in one launch; W row: [hi|hi|lo]
__global__ void convert_w_all(const float* __restrict__ w_in,
                              const float* __restrict__ w_out,
                              __nv_bfloat16* __restrict__ oq,
                              __nv_bfloat16* __restrict__ ok,
                              __nv_bfloat16* __restrict__ ov,
                              __nv_bfloat16* __restrict__ oo) {
    int idx = blockIdx.x * blockDim.x + threadIdx.x;   // over NEXP*64
    if (idx >= NEXP * 64) return;
    int n = idx >> 6, k4 = (idx & 63) << 2;
    int e = n >> 8, o = n & 255;
    long base = (long)n * KCAT + k4;
    __nv_bfloat16* dsts[3] = {oq, ok, ov};
    #pragma unroll
    for (int sec = 0; sec < 3; sec++) {
        float4 f = *(const float4*)(w_in + ((long)e * 768 + sec * 256 + o) * 256 + k4);
        uint32_t h01, l01, h23, l23;
        split2(f.x, f.y, h01, l01);
        split2(f.z, f.w, h23, l23);
        __nv_bfloat16* d = dsts[sec];
        *(uint2*)(d + base)       = make_uint2(h01, h23);
        *(uint2*)(d + base + 256) = make_uint2(h01, h23);
        *(uint2*)(d + base + 512) = make_uint2(l01, l23);
    }
    {
        float4 f = *(const float4*)(w_out + ((long)e * 256 + o) * 256 + k4);
        uint32_t h01, l01, h23, l23;
        split2(f.x, f.y, h01, l01);
        split2(f.z, f.w, h23, l23);
        *(uint2*)(oo + base)       = make_uint2(h01, h23);
        *(uint2*)(oo + base + 256) = make_uint2(h01, h23);
        *(uint2*)(oo + base + 512) = make_uint2(l01, l23);
    }
}

// ---------------- HMMA GEMM: 256x128 tile, 256 thr (8 warps, 64x64 warp tile)
#define TM 256
#define TN 128
#define STG 49152
#define GEMM_SMEM (3*STG)

__device__ __forceinline__ void gemm_issue(uint32_t smb, int c,
                                           const __nv_bfloat16* A,
                                           const __nv_bfloat16* Wb,
                                           int m0, int M, int tid) {
    uint32_t st = smb + (c % 3) * STG;
    // A chunk source: chunks 0-3 hi, 4-7 lo, 8-11 hi again
    int ko = (c < 4) ? c * 64 : (c < 8) ? 256 + (c - 4) * 64 : (c - 8) * 64;
    int kw = c * 64;
    #pragma unroll
    for (int i = 0; i < 8; i++) {
        int idx = tid + i * 256, row = idx >> 3, seg = idx & 7;
        int m = m0 + row;
        cp16(st + sw(row * 128 + seg * 16),
             A + (long)m * KA + ko + seg * 8, m < M);
    }
    #pragma unroll
    for (int i = 0; i < 4; i++) {
        int idx = tid + i * 256, row = idx >> 3, seg = idx & 7;
        cp16(st + TM * 128 + sw(row * 128 + seg * 16),
             Wb + (long)row * KCAT + kw + seg * 8, true);
    }
    CP_COMMIT();
}

__global__ void __launch_bounds__(256)
gemm_mma(const __nv_bfloat16* __restrict__ A, const __nv_bfloat16* __restrict__ W,
         const float* __restrict__ bias, float* __restrict__ C,
         int M, int ldc,
         long aZ, long wZ, int bZ, long cZ, int bES, int bSO) {
    extern __shared__ char smc[];
    uint32_t smb = smem_u32(smc);
    int tid = threadIdx.x, wid = tid >> 5, lane = tid & 31;
    int z = blockIdx.z;
    A += z * aZ;
    C += z * cZ;
    int m0 = blockIdx.x * TM;
    int n0 = blockIdx.y * TN;
    const __nv_bfloat16* Wb = W + z * wZ + (long)n0 * KCAT;

    int wm = wid >> 1, wn = wid & 1;   // 4x2 warp grid, 64x64 warp tile
    float acc[4][8][4];
    #pragma unroll
    for (int i = 0; i < 4; i++)
        #pragma unroll
        for (int j = 0; j < 8; j++)
            #pragma unroll
            for (int q = 0; q < 4; q++) acc[i][j][q] = 0.f;

    gemm_issue(smb, 0, A, Wb, m0, M, tid);
    gemm_issue(smb, 1, A, Wb, m0, M, tid);

    for (int c = 0; c < NCHUNK; c++) {
        if (c + 2 < NCHUNK) { gemm_issue(smb, c + 2, A, Wb, m0, M, tid); CP_WAIT2(); }
        else if (c + 1 < NCHUNK) { CP_WAIT1(); }
        else { CP_WAIT0(); }
        __syncthreads();

        uint32_t stA = smb + (c % 3) * STG;
        uint32_t stB = stA + TM * 128;
        #pragma unroll
        for (int ks = 0; ks < 4; ks++) {
            uint32_t a[4][4];
            #pragma unroll
            for (int mi = 0; mi < 4; mi++) {
                int r = wm * 64 + mi * 16 + (lane & 7) + ((lane >> 3) & 1) * 8;
                int cB = (ks * 16 + (lane >> 4) * 8) * 2;
                ldsm_x4(a[mi], stA + sw(r * 128 + cB));
            }
            uint32_t b[4][4];
            #pragma unroll
            for (int ni = 0; ni < 4; ni++) {
                int r = wn * 64 + ni * 16 + (lane & 7) + (lane >> 4) * 8;
                int cB = (ks * 16 + ((lane >> 3) & 1) * 8) * 2;
                ldsm_x4(b[ni], stB + sw(r * 128 + cB));
            }
            #pragma unroll
            for (int mi = 0; mi < 4; mi++) {
                #pragma unroll
                for (int nj = 0; nj < 8; nj++) {
                    mma16816(acc[mi][nj], a[mi], &b[nj >> 1][(nj & 1) * 2]);
                }
            }
        }
        __syncthreads();
    }

    int tq = lane >> 2, tr = lane & 3;
    #pragma unroll
    for (int mi = 0; mi < 4; mi++) {
        #pragma unroll
        for (int nj = 0; nj < 8; nj++) {
            int gm = m0 + wm * 64 + mi * 16 + tq;
            int lc = n0 + wn * 64 + nj * 8 + tr * 2;
            int e = lc >> 8;
            int bidx = z * bZ + e * bES + bSO + (lc & 255);
            float bx = __ldg(bias + bidx);
            float by = __ldg(bias + bidx + 1);
            if (gm < M) {
                float2 o = make_float2(acc[mi][nj][0] + bx, acc[mi][nj][1] + by);
                *(float2*)(C + (long)gm * ldc + lc) = o;
            }
            if (gm + 8 < M) {
                float2 o = make_float2(acc[mi][nj][2] + bx, acc[mi][nj][3] + by);
                *(float2*)(C + (long)(gm + 8) * ldc + lc) = o;
            }
        }
    }
}

// ---------------- gate: softmax over 5 experts per token -------------------
__global__ void gate_kernel(const float* __restrict__ tgt,
                            const float* __restrict__ wg,
                            const float* __restrict__ bg) {
    int warp = (blockIdx.x * blockDim.x + threadIdx.x) >> 5;
    int lane = threadIdx.x & 31;
    if (warp >= MQ) return;
    const float* x = tgt + warp * D;
    float logit[NE];
    #pragma unroll
    for (int e = 0; e < NE; e++) {
        float s = 0.f;
        #pragma unroll
        for (int k = lane; k < D; k += 32) s = fmaf(x[k], wg[e*D + k], s);
        #pragma unroll
        for (int o = 16; o > 0; o >>= 1) s += __shfl_xor_sync(0xffffffffu, s, o);
        logit[e] = s + bg[e];
    }
    if (lane == 0) {
        float mx = logit[0];
        #pragma unroll
        for (int e = 1; e < NE; e++) mx = fmaxf(mx, logit[e]);
        float p[NE], sum = 0.f;
        #pragma unroll
        for (int e = 0; e < NE; e++) { p[e] = __expf(logit[e] - mx); sum += p[e]; }
        float inv = 1.f / sum;
        #pragma unroll
        for (int e = 0; e < NE; e++) g_gate[warp*NE + e] = p[e] * inv;
    }
}

// ---------------- tensor-core flash attention -------------------------------
#define QROW 208
#define VROW 80
#define SM_Q  0
#define SM_K  26624
#define SM_VH 53248
#define SM_VL 63488
#define ATT_SMEM 73728

__global__ void __launch_bounds__(128) attn_mma() {
    extern __shared__ char smc[];
    uint32_t smb = smem_u32(smc);
    int h = blockIdx.x, b = blockIdx.y, e = blockIdx.z;
    int tid = threadIdx.x, wid = tid >> 5, lane = tid & 31;
    const float scale = 0.17677669529663688f;  // 1/sqrt(32)
    const float* gK = g_KV;
    const float* gV = g_KV + (long)MK * NEXP;

    {
        uint32_t qoff = smb + SM_Q + tid * QROW;
        if (tid < LQ) {
            const float4* qp = (const float4*)(g_Q + ((long)(tid * BB + b)) * NEXP
                                               + e * D + h * HD);
            #pragma unroll
            for (int j = 0; j < 8; j++) {
                float4 f = qp[j];
                uint32_t h01, l01, h23, l23;
                split2(f.x * scale, f.y * scale, h01, l01);
                split2(f.z * scale, f.w * scale, h23, l23);
                uint2 hv = make_uint2(h01, h23), lv = make_uint2(l01, l23);
                *(uint2*)(smc + (qoff - smb) + j * 8)       = hv;
                *(uint2*)(smc + (qoff - smb) + 64 + j * 8)  = lv;
                *(uint2*)(smc + (qoff - smb) + 128 + j * 8) = hv;
            }
        } else {
            uint2 z = make_uint2(0, 0);
            #pragma unroll
            for (int j = 0; j < 24; j++)
                *(uint2*)(smc + (qoff - smb) + j * 8) = z;
        }
    }

    float mst[2][2], lst[2][2], O[2][4][4];
    #pragma unroll
    for (int mt = 0; mt < 2; mt++) {
        mst[mt][0] = -INFINITY; mst[mt][1] = -INFINITY;
        lst[mt][0] = 0.f; lst[mt][1] = 0.f;
        #pragma unroll
        for (int nt = 0; nt < 4; nt++)
            #pragma unroll
            for (int q = 0; q < 4; q++) O[mt][nt][q] = 0.f;
    }

    for (int s0 = 0; s0 < LK; s0 += 128) {
        __syncthreads();
        {
            long base = ((long)((s0 + tid) * BB + b)) * NEXP + e * D + h * HD;
            const float4* kp = (const float4*)(gK + base);
            const float4* vp = (const float4*)(gV + base);
            char* krow = smc + SM_K + tid * QROW;
            char* vhrow = smc + SM_VH + tid * VROW;
            char* vlrow = smc + SM_VL + tid * VROW;
            #pragma unroll
            for (int j = 0; j < 8; j++) {
                float4 f = kp[j];
                uint32_t h01, l01, h23, l23;
                split2(f.x, f.y, h01, l01);
                split2(f.z, f.w, h23, l23);
                uint2 hv = make_uint2(h01, h23), lv = make_uint2(l01, l23);
                *(uint2*)(krow + j * 8)       = hv;
                *(uint2*)(krow + 64 + j * 8)  = hv;
                *(uint2*)(krow + 128 + j * 8) = lv;
                f = vp[j];
                split2(f.x, f.y, h01, l01);
                split2(f.z, f.w, h23, l23);
                *(uint2*)(vhrow + j * 8) = make_uint2(h01, h23);
                *(uint2*)(vlrow + j * 8) = make_uint2(l01, l23);
            }
        }
        __syncthreads();

        #pragma unroll
        for (int mt = 0; mt < 2; mt++) {
            int m0 = wid * 32 + mt * 16;
            uint32_t aq[6][4];
            #pragma unroll
            for (int kk = 0; kk < 6; kk++)
                ldsm_x4(aq[kk], smb + SM_Q + (m0 + (lane & 15)) * QROW
                                 + kk * 32 + (lane >> 4) * 16);
            float S[16][4];
            #pragma unroll
            for (int nt = 0; nt < 16; nt++)
                #pragma unroll
                for (int q = 0; q < 4; q++) S[nt][q] = 0.f;
            #pragma unroll
            for (int ng = 0; ng < 8; ng++) {
                #pragma unroll
                for (int kk = 0; kk < 6; kk++) {
                    uint32_t bk[4];
                    ldsm_x4(bk, smb + SM_K
                            + (ng * 16 + (lane & 7) + ((lane >> 4) << 3)) * QROW
                            + kk * 32 + (((lane >> 3) & 1) << 4));
                    mma16816(S[2 * ng],     aq[kk], bk);
                    mma16816(S[2 * ng + 1], aq[kk], bk + 2);
                }
            }
            float vA = -INFINITY, vB = -INFINITY;
            #pragma unroll
            for (int nt = 0; nt < 16; nt++) {
                vA = fmaxf(vA, fmaxf(S[nt][0], S[nt][1]));
                vB = fmaxf(vB, fmaxf(S[nt][2], S[nt][3]));
            }
            vA = fmaxf(vA, __shfl_xor_sync(0xffffffffu, vA, 1));
            vA = fmaxf(vA, __shfl_xor_sync(0xffffffffu, vA, 2));
            vB = fmaxf(vB, __shfl_xor_sync(0xffffffffu, vB, 1));
            vB = fmaxf(vB, __shfl_xor_sync(0xffffffffu, vB, 2));
            float mnA = fmaxf(mst[mt][0], vA), mnB = fmaxf(mst[mt][1], vB);
            float fA = __expf(mst[mt][0] - mnA), fB = __expf(mst[mt][1] - mnB);
            mst[mt][0] = mnA; mst[mt][1] = mnB;
            float sA = 0.f, sB = 0.f;
            #pragma unroll
            for (int nt = 0; nt < 16; nt++) {
                S[nt][0] = __expf(S[nt][0] - mnA);
                S[nt][1] = __expf(S[nt][1] - mnA);
                S[nt][2] = __expf(S[nt][2] - mnB);
                S[nt][3] = __expf(S[nt][3] - mnB);
                sA += S[nt][0] + S[nt][1];
                sB += S[nt][2] + S[nt][3];
            }
            sA += __shfl_xor_sync(0xffffffffu, sA, 1);
            sA += __shfl_xor_sync(0xffffffffu, sA, 2);
            sB += __shfl_xor_sync(0xffffffffu, sB, 1);
            sB += __shfl_xor_sync(0xffffffffu, sB, 2);
            lst[mt][0] = lst[mt][0] * fA + sA;
            lst[mt][1] = lst[mt][1] * fB + sB;
            #pragma unroll
            for (int nt = 0; nt < 4; nt++) {
                O[mt][nt][0] *= fA; O[mt][nt][1] *= fA;
                O[mt][nt][2] *= fB; O[mt][nt][3] *= fB;
            }
            #pragma unroll
            for (int kt = 0; kt < 8; kt++) {
                uint32_t phi[4], plo[4];
                phi[0] = packbf2(S[2*kt][0],   S[2*kt][1]);
                phi[1] = packbf2(S[2*kt][2],   S[2*kt][3]);
                phi[2] = packbf2(S[2*kt+1][0], S[2*kt+1][1]);
                phi[3] = packbf2(S[2*kt+1][2], S[2*kt+1][3]);
                #pragma unroll
                for (int i = 0; i < 4; i++) {
                    __nv_bfloat162 hp = *(__nv_bfloat162*)&phi[i];
                    int nt = 2*kt + (i >> 1), q = (i & 1) * 2;
                    plo[i] = packbf2(S[nt][q]   - __bfloat162float(hp.x),
                                     S[nt][q+1] - __bfloat162float(hp.y));
                }
                uint32_t vrow = kt * 16 + (lane & 15);
                uint32_t bh0[4], bh1[4], bl0[4], bl1[4];
                ldsm_x4_t(bh0, smb + SM_VH + vrow * VROW + (lane >> 4) * 16);
                ldsm_x4_t(bh1, smb + SM_VH + vrow * VROW + 32 + (lane >> 4) * 16);
                ldsm_x4_t(bl0, smb + SM_VL + vrow * VROW + (lane >> 4) * 16);
                ldsm_x4_t(bl1, smb + SM_VL + vrow * VROW + 32 + (lane >> 4) * 16);
                mma16816(O[mt][0], phi, bh0); mma16816(O[mt][1], phi, bh0 + 2);
                mma16816(O[mt][2], phi, bh1); mma16816(O[mt][3], phi, bh1 + 2);
                mma16816(O[mt][0], plo, bh0); mma16816(O[mt][1], plo, bh0 + 2);
                mma16816(O[mt][2], plo, bh1); mma16816(O[mt][3], plo, bh1 + 2);
                mma16816(O[mt][0], phi, bl0); mma16816(O[mt][1], phi, bl0 + 2);
                mma16816(O[mt][2], phi, bl1); mma16816(O[mt][3], phi, bl1 + 2);
            }
        }
    }

    int r = lane >> 2, c = (lane & 3) * 2;
    #pragma unroll
    for (int mt = 0; mt < 2; mt++) {
        float invA = 1.f / lst[mt][0];
        float invB = 1.f / lst[mt][1];
        int qA = wid * 32 + mt * 16 + r;
        int qB = qA + 8;
        #pragma unroll
        for (int nt = 0; nt < 4; nt++) {
            if (qA < LQ) {
                float* cp = g_ctx + ((long)e * MQ + qA * BB + b) * D + h * HD
                            + nt * 8 + c;
                *(float2*)cp = make_float2(O[mt][nt][0] * invA,
                                           O[mt][nt][1] * invA);
            }
            if (qB < LQ) {
                float* cp = g_ctx + ((long)e * MQ + qB * BB + b) * D + h * HD
                            + nt * 8 + c;
                *(float2*)cp = make_float2(O[mt][nt][2] * invB,
                                           O[mt][nt][3] * invB);
            }
        }
    }
}

// ---------------- gated combine + residual + LayerNorm ---------------------
__global__ void __launch_bounds__(256)
combine_ln(const float* __restrict__ tgt,
           const float* __restrict__ gamma,
           const float* __restrict__ beta,
           float* __restrict__ out) {
    int m = blockIdx.x;
    int k = threadIdx.x;
    float g[NE];
    #pragma unroll
    for (int e = 0; e < NE; e++) g[e] = g_gate[m*NE + e];
    float x = tgt[(long)m * D + k];
    #pragma unroll
    for (int e = 0; e < NE; e++)
        x = fmaf(g[e], g_out[(long)e * MQ * D + (long)m * D + k], x);

    __shared__ float red[16];
    float s = x, s2 = x * x;
    #pragma unroll
    for (int o = 16; o > 0; o >>= 1) {
        s  += __shfl_xor_sync(0xffffffffu, s, o);
        s2 += __shfl_xor_sync(0xffffffffu, s2, o);
    }
    int wid = k >> 5, lane = k & 31;
    if (lane == 0) { red[wid] = s; red[8 + wid] = s2; }
    __syncthreads();
    if (k < 32) {
        float a  = (k < 8) ? red[k]     : 0.f;
        float b2 = (k < 8) ? red[8 + k] : 0.f;
        #pragma unroll
        for (int o = 4; o > 0; o >>= 1) {
            a  += __shfl_xor_sync(0xffffffffu, a,  o);
            b2 += __shfl_xor_sync(0xffffffffu, b2, o);
        }
        if (k == 0) { red[0] = a; red[1] = b2; }
    }
    __syncthreads();
    float mu  = red[0] * (1.f / D);
    float var = red[1] * (1.f / D) - mu * mu;
    float r = rsqrtf(var + 1e-5f);
    out[(long)m * D + k] = (x - mu) * r * gamma[k] + beta[k];
}

// ---------------- launch ----------------------------------------------------
extern "C" void kernel_launch(void* const* d_in, const int* in_sizes, int n_in,
                              void* d_out, int out_size) {
    const float* tgt    = (const float*)d_in[0];
    const float* memory = (const float*)d_in[1];
    const float* qpos   = (const float*)d_in[2];
    const float* pos    = (const float*)d_in[3];
    const float* w_in   = (const float*)d_in[4];
    const float* b_in   = (const float*)d_in[5];
    const float* w_out  = (const float*)d_in[6];
    const float* b_out  = (const float*)d_in[7];
    const float* w_gate = (const float*)d_in[8];
    const float* b_gate = (const float*)d_in[9];
    const float* gamma  = (const float*)d_in[10];
    const float* beta   = (const float*)d_in[11];

    float *pQ, *pKV, *pCtx, *pOut;
    __nv_bfloat16 *pAq, *pAkv, *pAc, *pWq, *pWkv, *pWo;
    cudaGetSymbolAddress((void**)&pQ,   g_Q);
    cudaGetSymbolAddress((void**)&pKV,  g_KV);
    cudaGetSymbolAddress((void**)&pCtx, g_ctx);
    cudaGetSymbolAddress((void**)&pOut, g_out);
    cudaGetSymbolAddress((void**)&pAq,  g_Aq);
    cudaGetSymbolAddress((void**)&pAkv, g_Akv);
    cudaGetSymbolAddress((void**)&pAc,  g_Ac);
    cudaGetSymbolAddress((void**)&pWq,  g_Wq);
    cudaGetSymbolAddress((void**)&pWkv, g_Wkv);
    cudaGetSymbolAddress((void**)&pWo,  g_Wo);

    cudaFuncSetAttribute(gemm_mma, cudaFuncAttributeMaxDynamicSharedMemorySize, GEMM_SMEM);
    cudaFuncSetAttribute(attn_mma, cudaFuncAttributeMaxDynamicSharedMemorySize, ATT_SMEM);

    // 0: K/V activation conversion
    convert_kv<<<(MK*64 + 255)/256, 256>>>(memory, pos, pAkv, pAkv + (long)MK*KA);
    // 1: all weight conversions
    convert_w_all<<<(NEXP*64 + 255)/256, 256>>>(w_in, w_out, pWq, pWkv,
                                                pWkv + (long)NEXP*KCAT, pWo);
    // 2: Q activation conversion
    convert_act<<<(MQ*64 + 255)/256, 256>>>(tgt, qpos, pAq, MQ);

    // 3: merged K+V projection GEMM (z=0 -> K, z=1 -> V)  [profiled slot]
    gemm_mma<<<dim3(64, 10, 2), 256, GEMM_SMEM>>>(
        pAkv, pWkv, b_in, pKV, MK, NEXP,
        (long)MK*KA, (long)NEXP*KCAT, 256, (long)MK*NEXP, 768, 256);

    // 4: Q projection
    gemm_mma<<<dim3(7, 10, 1), 256, GEMM_SMEM>>>(pAq, pWq, b_in, pQ, MQ, NEXP,
                                                 0, 0, 0, 0, 768, 0);
    // 5: gate softmax
    gate_kernel<<<(MQ*32 + 127)/128, 128>>>(tgt, w_gate, b_gate);

    // 6: tensor-core flash attention
    attn_mma<<<dim3(NH, BB, NE), 128, ATT_SMEM>>>();

    // 7: ctx conversion
    convert_act<<<(NE*MQ*64 + 255)/256, 256>>>(pCtx, nullptr, pAc, NE*MQ);

    // 8: out projection (per expert via grid.z)
    gemm_mma<<<dim3(7, 2, 5), 256, GEMM_SMEM>>>(pAc, pWo, b_out, pOut, MQ, D,
                                                (long)MQ*KA, (long)D*KCAT,
                                                D, (long)MQ*D, 0, 0);

    // 9: gated combine + residual + LN
    combine_ln<<<MQ, 256>>>(tgt, gamma, beta, (float*)d_out);
}

// round 8
// speedup vs baseline: 1.1896x; 1.1896x over previous
#include <cuda_runtime.h>
#include <cuda_bf16.h>
#include <cuda_fp16.h>
#include <math.h>
#include <cstdint>

// Problem constants
#define D      256
#define NH     8
#define HD     32
#define NE     5
#define LQ     100
#define LK     1024
#define BB     16
#define MQ     (LQ*BB)      // 1600
#define MK     (LK*BB)      // 16384
#define NEXP   (NE*D)       // 1280
#define KA     512          // A cat: [hi(256)|lo(256)] fp16
#define KW     256          // W: single fp16, re-read for chunks 4-7
#define NCHUNK 8

// ---------------- scratch (device globals) ---------------------------------
__device__ float g_Q[MQ*NEXP];
__device__ float g_KV[2L*MK*NEXP];          // [0]=K, [1]=V
__device__ float g_gate[MQ*NE];
__device__ float g_ctx[NE*MQ*D];
__device__ float g_out[NE*MQ*D];

__device__ __half g_Aq[MQ*KA];
__device__ __half g_Akv[2L*MK*KA];          // [0]=K-act, [1]=V-act
__device__ __half g_Ac[NE*MQ*KA];
__device__ __half g_Wq[NEXP*KW];
__device__ __half g_Wkv[2L*NEXP*KW];        // [0]=Wk, [1]=Wv
__device__ __half g_Wo[NEXP*KW];

// ---------------- helpers ----------------------------------------------------
__device__ __forceinline__ uint32_t smem_u32(const void* p) {
    uint32_t a;
    asm("{ .reg .u64 t; cvta.to.shared.u64 t, %1; cvt.u32.u64 %0, t; }"
        : "=r"(a) : "l"(p));
    return a;
}

__device__ __forceinline__ uint32_t sw(uint32_t off) {
    return off ^ ((off >> 3) & 0x70);
}

__device__ __forceinline__ void cp16(uint32_t dst, const void* src, bool pred) {
    int sz = pred ? 16 : 0;
    asm volatile("cp.async.cg.shared.global [%0], [%1], 16, %2;"
                 :: "r"(dst), "l"(src), "r"(sz));
}
#define CP_COMMIT() asm volatile("cp.async.commit_group;" ::: "memory")
#define CP_WAIT2()  asm volatile("cp.async.wait_group 2;" ::: "memory")
#define CP_WAIT1()  asm volatile("cp.async.wait_group 1;" ::: "memory")
#define CP_WAIT0()  asm volatile("cp.async.wait_group 0;" ::: "memory")

__device__ __forceinline__ void ldsm_x4(uint32_t* r, uint32_t addr) {
    asm volatile("ldmatrix.sync.aligned.m8n8.x4.shared.b16 {%0,%1,%2,%3}, [%4];"
                 : "=r"(r[0]), "=r"(r[1]), "=r"(r[2]), "=r"(r[3]) : "r"(addr));
}

__device__ __forceinline__ void ldsm_x4_t(uint32_t* r, uint32_t addr) {
    asm volatile("ldmatrix.sync.aligned.m8n8.x4.trans.shared.b16 {%0,%1,%2,%3}, [%4];"
                 : "=r"(r[0]), "=r"(r[1]), "=r"(r[2]), "=r"(r[3]) : "r"(addr));
}

// bf16 MMA (attention)
__device__ __forceinline__ void mma16816(float* d, const uint32_t* a,
                                         const uint32_t* b) {
    asm volatile(
        "mma.sync.aligned.m16n8k16.row.col.f32.bf16.bf16.f32 "
        "{%0,%1,%2,%3}, {%4,%5,%6,%7}, {%8,%9}, {%0,%1,%2,%3};"
        : "+f"(d[0]), "+f"(d[1]), "+f"(d[2]), "+f"(d[3])
        : "r"(a[0]), "r"(a[1]), "r"(a[2]), "r"(a[3]), "r"(b[0]), "r"(b[1]));
}

// fp16 MMA (projections)
__device__ __forceinline__ void mma16816h(float* d, const uint32_t* a,
                                          const uint32_t* b) {
    asm volatile(
        "mma.sync.aligned.m16n8k16.row.col.f32.f16.f16.f32 "
        "{%0,%1,%2,%3}, {%4,%5,%6,%7}, {%8,%9}, {%0,%1,%2,%3};"
        : "+f"(d[0]), "+f"(d[1]), "+f"(d[2]), "+f"(d[3])
        : "r"(a[0]), "r"(a[1]), "r"(a[2]), "r"(a[3]), "r"(b[0]), "r"(b[1]));
}

__device__ __forceinline__ uint32_t packbf2(float x, float y) {
    uint32_t d;
    asm("cvt.rn.bf16x2.f32 %0, %1, %2;" : "=r"(d) : "f"(y), "f"(x));
    return d;
}

__device__ __forceinline__ void split2(float x, float y, uint32_t& hi, uint32_t& lo) {
    hi = packbf2(x, y);
    __nv_bfloat162 h = *(__nv_bfloat162*)&hi;
    lo = packbf2(x - __bfloat162float(h.x), y - __bfloat162float(h.y));
}

__device__ __forceinline__ uint32_t packh2(float x, float y) {
    uint32_t d;
    asm("cvt.rn.f16x2.f32 %0, %1, %2;" : "=r"(d) : "f"(y), "f"(x));
    return d;
}

__device__ __forceinline__ void splith2(float x, float y, uint32_t& hi, uint32_t& lo) {
    hi = packh2(x, y);
    __half2 h = *(__half2*)&hi;
    lo = packh2(x - __half2float(h.x), y - __half2float(h.y));
}

// ---------------- fp16 conversions (vectorized) ------------------------------
// A row layout: [hi(256) | lo(256)] fp16
__global__ void convert_act(const float* __restrict__ a,
                            const float* __restrict__ b,
                            __half* __restrict__ out, int M) {
    int idx = blockIdx.x * blockDim.x + threadIdx.x;   // over M*64 float4s
    if (idx >= M * 64) return;
    int m = idx >> 6, k4 = (idx & 63) << 2;
    float4 f = *(const float4*)(a + (long)idx * 4);
    if (b) {
        float4 g = *(const float4*)(b + (long)idx * 4);
        f.x += g.x; f.y += g.y; f.z += g.z; f.w += g.w;
    }
    uint32_t h01, l01, h23, l23;
    splith2(f.x, f.y, h01, l01);
    splith2(f.z, f.w, h23, l23);
    long base = (long)m * KA + k4;
    *(uint2*)(out + base)       = make_uint2(h01, h23);
    *(uint2*)(out + base + 256) = make_uint2(l01, l23);
}

// fused K/V conversion: reads memory (+pos) once
__global__ void convert_kv(const float* __restrict__ mem,
                           const float* __restrict__ pos,
                           __half* __restrict__ outK,
                           __half* __restrict__ outV) {
    int idx = blockIdx.x * blockDim.x + threadIdx.x;
    if (idx >= MK * 64) return;
    int m = idx >> 6, k4 = (idx & 63) << 2;
    float4 v = *(const float4*)(mem + (long)idx * 4);
    float4 p = *(const float4*)(pos + (long)idx * 4);
    long base = (long)m * KA + k4;
    uint32_t h01, l01, h23, l23;
    splith2(v.x + p.x, v.y + p.y, h01, l01);
    splith2(v.z + p.z, v.w + p.w, h23, l23);
    *(uint2*)(outK + base)       = make_uint2(h01, h23);
    *(uint2*)(outK + base + 256) = make_uint2(l01, l23);
    splith2(v.x, v.y, h01, l01);
    splith2(v.z, v.w, h23, l23);
    *(uint2*)(outV + base)       = make_uint2(h01, h23);
    *(uint2*)(outV + base + 256) = make_uint2(l01, l23);
}

// all four weight tensors in one launch; W stored once as fp16 (width 256)
__global__ void convert_w_all(const float* __restrict__ w_in,
                              const float* __restrict__ w_out,
                              __half* __restrict__ oq,
                              __half* __restrict__ ok,
                              __half* __restrict__ ov,
                              __half* __restrict__ oo) {
    int idx = blockIdx.x * blockDim.x + threadIdx.x;   // over NEXP*64
    if (idx >= NEXP * 64) return;
    int n = idx >> 6, k4 = (idx & 63) << 2;
    int e = n >> 8, o = n & 255;
    long base = (long)n * KW + k4;
    __half* dsts[3] = {oq, ok, ov};
    #pragma unroll
    for (int sec = 0; sec < 3; sec++) {
        float4 f = *(const float4*)(w_in + ((long)e * 768 + sec * 256 + o) * 256 + k4);
        *(uint2*)(dsts[sec] + base) = make_uint2(packh2(f.x, f.y), packh2(f.z, f.w));
    }
    {
        float4 f = *(const float4*)(w_out + ((long)e * 256 + o) * 256 + k4);
        *(uint2*)(oo + base) = make_uint2(packh2(f.x, f.y), packh2(f.z, f.w));
    }
}

// ---------------- fp16 HMMA GEMM: 256x128 tile, 8 warps, 64x64 warp tile ----
#define TM 256
#define TN 128
#define STG 49152
#define GEMM_SMEM (3*STG)

__device__ __forceinline__ void gemm_issue(uint32_t smb, int c,
                                           const __half* A,
                                           const __half* Wb,
                                           int m0, int M, int tid) {
    uint32_t st = smb + (c % 3) * STG;
    int ko = c * 64;          // A: chunks 0-3 hi, 4-7 lo (contiguous in KA=512)
    int kw = (c & 3) * 64;    // W: single 256-wide tensor, re-read for c>=4
    #pragma unroll
    for (int i = 0; i < 8; i++) {
        int idx = tid + i * 256, row = idx >> 3, seg = idx & 7;
        int m = m0 + row;
        cp16(st + sw(row * 128 + seg * 16),
             A + (long)m * KA + ko + seg * 8, m < M);
    }
    #pragma unroll
    for (int i = 0; i < 4; i++) {
        int idx = tid + i * 256, row = idx >> 3, seg = idx & 7;
        cp16(st + TM * 128 + sw(row * 128 + seg * 16),
             Wb + (long)row * KW + kw + seg * 8, true);
    }
    CP_COMMIT();
}

__global__ void __launch_bounds__(256)
gemm_mma(const __half* __restrict__ A, const __half* __restrict__ W,
         const float* __restrict__ bias, float* __restrict__ C,
         int M, int ldc,
         long aZ, long wZ, int bZ, long cZ, int bES, int bSO) {
    extern __shared__ char smc[];
    uint32_t smb = smem_u32(smc);
    int tid = threadIdx.x, wid = tid >> 5, lane = tid & 31;
    int z = blockIdx.z;
    A += z * aZ;
    C += z * cZ;
    int m0 = blockIdx.x * TM;
    int n0 = blockIdx.y * TN;
    const __half* Wb = W + z * wZ + (long)n0 * KW;

    int wm = wid >> 1, wn = wid & 1;   // 4x2 warp grid, 64x64 warp tile
    float acc[4][8][4];
    #pragma unroll
    for (int i = 0; i < 4; i++)
        #pragma unroll
        for (int j = 0; j < 8; j++)
            #pragma unroll
            for (int q = 0; q < 4; q++) acc[i][j][q] = 0.f;

    gemm_issue(smb, 0, A, Wb, m0, M, tid);
    gemm_issue(smb, 1, A, Wb, m0, M, tid);

    for (int c = 0; c < NCHUNK; c++) {
        if (c + 2 < NCHUNK) { gemm_issue(smb, c + 2, A, Wb, m0, M, tid); CP_WAIT2(); }
        else if (c + 1 < NCHUNK) { CP_WAIT1(); }
        else { CP_WAIT0(); }
        __syncthreads();

        uint32_t stA = smb + (c % 3) * STG;
        uint32_t stB = stA + TM * 128;
        #pragma unroll
        for (int ks = 0; ks < 4; ks++) {
            uint32_t a[4][4];
            #pragma unroll
            for (int mi = 0; mi < 4; mi++) {
                int r = wm * 64 + mi * 16 + (lane & 7) + ((lane >> 3) & 1) * 8;
                int cB = (ks * 16 + (lane >> 4) * 8) * 2;
                ldsm_x4(a[mi], stA + sw(r * 128 + cB));
            }
            uint32_t b[4][4];
            #pragma unroll
            for (int ni = 0; ni < 4; ni++) {
                int r = wn * 64 + ni * 16 + (lane & 7) + (lane >> 4) * 8;
                int cB = (ks * 16 + ((lane >> 3) & 1) * 8) * 2;
                ldsm_x4(b[ni], stB + sw(r * 128 + cB));
            }
            #pragma unroll
            for (int mi = 0; mi < 4; mi++) {
                #pragma unroll
                for (int nj = 0; nj < 8; nj++) {
                    mma16816h(acc[mi][nj], a[mi], &b[nj >> 1][(nj & 1) * 2]);
                }
            }
        }
        __syncthreads();
    }

    int tq = lane >> 2, tr = lane & 3;
    #pragma unroll
    for (int mi = 0; mi < 4; mi++) {
        #pragma unroll
        for (int nj = 0; nj < 8; nj++) {
            int gm = m0 + wm * 64 + mi * 16 + tq;
            int lc = n0 + wn * 64 + nj * 8 + tr * 2;
            int e = lc >> 8;
            int bidx = z * bZ + e * bES + bSO + (lc & 255);
            float bx = __ldg(bias + bidx);
            float by = __ldg(bias + bidx + 1);
            if (gm < M) {
                float2 o = make_float2(acc[mi][nj][0] + bx, acc[mi][nj][1] + by);
                *(float2*)(C + (long)gm * ldc + lc) = o;
            }
            if (gm + 8 < M) {
                float2 o = make_float2(acc[mi][nj][2] + bx, acc[mi][nj][3] + by);
                *(float2*)(C + (long)(gm + 8) * ldc + lc) = o;
            }
        }
    }
}

// ---------------- gate: softmax over 5 experts per token -------------------
__global__ void gate_kernel(const float* __restrict__ tgt,
                            const float* __restrict__ wg,
                            const float* __restrict__ bg) {
    int warp = (blockIdx.x * blockDim.x + threadIdx.x) >> 5;
    int lane = threadIdx.x & 31;
    if (warp >= MQ) return;
    const float* x = tgt + warp * D;
    float logit[NE];
    #pragma unroll
    for (int e = 0; e < NE; e++) {
        float s = 0.f;
        #pragma unroll
        for (int k = lane; k < D; k += 32) s = fmaf(x[k], wg[e*D + k], s);
        #pragma unroll
        for (int o = 16; o > 0; o >>= 1) s += __shfl_xor_sync(0xffffffffu, s, o);
        logit[e] = s + bg[e];
    }
    if (lane == 0) {
        float mx = logit[0];
        #pragma unroll
        for (int e = 1; e < NE; e++) mx = fmaxf(mx, logit[e]);
        float p[NE], sum = 0.f;
        #pragma unroll
        for (int e = 0; e < NE; e++) { p[e] = __expf(logit[e] - mx); sum += p[e]; }
        float inv = 1.f / sum;
        #pragma unroll
        for (int e = 0; e < NE; e++) g_gate[warp*NE + e] = p[e] * inv;
    }
}

// ---------------- tensor-core flash attention (bf16 3-term, unchanged) ------
#define QROW 208
#define VROW 80
#define SM_Q  0
#define SM_K  26624
#define SM_VH 53248
#define SM_VL 63488
#define ATT_SMEM 73728

__global__ void __launch_bounds__(128) attn_mma() {
    extern __shared__ char smc[];
    uint32_t smb = smem_u32(smc);
    int h = blockIdx.x, b = blockIdx.y, e = blockIdx.z;
    int tid = threadIdx.x, wid = tid >> 5, lane = tid & 31;
    const float scale = 0.17677669529663688f;  // 1/sqrt(32)
    const float* gK = g_KV;
    const float* gV = g_KV + (long)MK * NEXP;

    {
        uint32_t qoff = smb + SM_Q + tid * QROW;
        if (tid < LQ) {
            const float4* qp = (const float4*)(g_Q + ((long)(tid * BB + b)) * NEXP
                                               + e * D + h * HD);
            #pragma unroll
            for (int j = 0; j < 8; j++) {
                float4 f = qp[j];
                uint32_t h01, l01, h23, l23;
                split2(f.x * scale, f.y * scale, h01, l01);
                split2(f.z * scale, f.w * scale, h23, l23);
                uint2 hv = make_uint2(h01, h23), lv = make_uint2(l01, l23);
                *(uint2*)(smc + (qoff - smb) + j * 8)       = hv;
                *(uint2*)(smc + (qoff - smb) + 64 + j * 8)  = lv;
                *(uint2*)(smc + (qoff - smb) + 128 + j * 8) = hv;
            }
        } else {
            uint2 z = make_uint2(0, 0);
            #pragma unroll
            for (int j = 0; j < 24; j++)
                *(uint2*)(smc + (qoff - smb) + j * 8) = z;
        }
    }

    float mst[2][2], lst[2][2], O[2][4][4];
    #pragma unroll
    for (int mt = 0; mt < 2; mt++) {
        mst[mt][0] = -INFINITY; mst[mt][1] = -INFINITY;
        lst[mt][0] = 0.f; lst[mt][1] = 0.f;
        #pragma unroll
        for (int nt = 0; nt < 4; nt++)
            #pragma unroll
            for (int q = 0; q < 4; q++) O[mt][nt][q] = 0.f;
    }

    for (int s0 = 0; s0 < LK; s0 += 128) {
        __syncthreads();
        {
            long base = ((long)((s0 + tid) * BB + b)) * NEXP + e * D + h * HD;
            const float4* kp = (const float4*)(gK + base);
            const float4* vp = (const float4*)(gV + base);
            char* krow = smc + SM_K + tid * QROW;
            char* vhrow = smc + SM_VH + tid * VROW;
            char* vlrow = smc + SM_VL + tid * VROW;
            #pragma unroll
            for (int j = 0; j < 8; j++) {
                float4 f = kp[j];
                uint32_t h01, l01, h23, l23;
                split2(f.x, f.y, h01, l01);
                split2(f.z, f.w, h23, l23);
                uint2 hv = make_uint2(h01, h23), lv = make_uint2(l01, l23);
                *(uint2*)(krow + j * 8)       = hv;
                *(uint2*)(krow + 64 + j * 8)  = hv;
                *(uint2*)(krow + 128 + j * 8) = lv;
                f = vp[j];
                split2(f.x, f.y, h01, l01);
                split2(f.z, f.w, h23, l23);
                *(uint2*)(vhrow + j * 8) = make_uint2(h01, h23);
                *(uint2*)(vlrow + j * 8) = make_uint2(l01, l23);
            }
        }
        __syncthreads();

        #pragma unroll
        for (int mt = 0; mt < 2; mt++) {
            int m0 = wid * 32 + mt * 16;
            uint32_t aq[6][4];
            #pragma unroll
            for (int kk = 0; kk < 6; kk++)
                ldsm_x4(aq[kk], smb + SM_Q + (m0 + (lane & 15)) * QROW
                                 + kk * 32 + (lane >> 4) * 16);
            float S[16][4];
            #pragma unroll
            for (int nt = 0; nt < 16; nt++)
                #pragma unroll
                for (int q = 0; q < 4; q++) S[nt][q] = 0.f;
            #pragma unroll
            for (int ng = 0; ng < 8; ng++) {
                #pragma unroll
                for (int kk = 0; kk < 6; kk++) {
                    uint32_t bk[4];
                    ldsm_x4(bk, smb + SM_K
                            + (ng * 16 + (lane & 7) + ((lane >> 4) << 3)) * QROW
                            + kk * 32 + (((lane >> 3) & 1) << 4));
                    mma16816(S[2 * ng],     aq[kk], bk);
                    mma16816(S[2 * ng + 1], aq[kk], bk + 2);
                }
            }
            float vA = -INFINITY, vB = -INFINITY;
            #pragma unroll
            for (int nt = 0; nt < 16; nt++) {
                vA = fmaxf(vA, fmaxf(S[nt][0], S[nt][1]));
                vB = fmaxf(vB, fmaxf(S[nt][2], S[nt][3]));
            }
            vA = fmaxf(vA, __shfl_xor_sync(0xffffffffu, vA, 1));
            vA = fmaxf(vA, __shfl_xor_sync(0xffffffffu, vA, 2));
            vB = fmaxf(vB, __shfl_xor_sync(0xffffffffu, vB, 1));
            vB = fmaxf(vB, __shfl_xor_sync(0xffffffffu, vB, 2));
            float mnA = fmaxf(mst[mt][0], vA), mnB = fmaxf(mst[mt][1], vB);
            float fA = __expf(mst[mt][0] - mnA), fB = __expf(mst[mt][1] - mnB);
            mst[mt][0] = mnA; mst[mt][1] = mnB;
            float sA = 0.f, sB = 0.f;
            #pragma unroll
            for (int nt = 0; nt < 16; nt++) {
                S[nt][0] = __expf(S[nt][0] - mnA);
                S[nt][1] = __expf(S[nt][1] - mnA);
                S[nt][2] = __expf(S[nt][2] - mnB);
                S[nt][3] = __expf(S[nt][3] - mnB);
                sA += S[nt][0] + S[nt][1];
                sB += S[nt][2] + S[nt][3];
            }
            sA += __shfl_xor_sync(0xffffffffu, sA, 1);
            sA += __shfl_xor_sync(0xffffffffu, sA, 2);
            sB += __shfl_xor_sync(0xffffffffu, sB, 1);
            sB += __shfl_xor_sync(0xffffffffu, sB, 2);
            lst[mt][0] = lst[mt][0] * fA + sA;
            lst[mt][1] = lst[mt][1] * fB + sB;
            #pragma unroll
            for (int nt = 0; nt < 4; nt++) {
                O[mt][nt][0] *= fA; O[mt][nt][1] *= fA;
                O[mt][nt][2] *= fB; O[mt][nt][3] *= fB;
            }
            #pragma unroll
            for (int kt = 0; kt < 8; kt++) {
                uint32_t phi[4], plo[4];
                phi[0] = packbf2(S[2*kt][0],   S[2*kt][1]);
                phi[1] = packbf2(S[2*kt][2],   S[2*kt][3]);
                phi[2] = packbf2(S[2*kt+1][0], S[2*kt+1][1]);
                phi[3] = packbf2(S[2*kt+1][2], S[2*kt+1][3]);
                #pragma unroll
                for (int i = 0; i < 4; i++) {
                    __nv_bfloat162 hp = *(__nv_bfloat162*)&phi[i];
                    int nt = 2*kt + (i >> 1), q = (i & 1) * 2;
                    plo[i] = packbf2(S[nt][q]   - __bfloat162float(hp.x),
                                     S[nt][q+1] - __bfloat162float(hp.y));
                }
                uint32_t vrow = kt * 16 + (lane & 15);
                uint32_t bh0[4], bh1[4], bl0[4], bl1[4];
                ldsm_x4_t(bh0, smb + SM_VH + vrow * VROW + (lane >> 4) * 16);
                ldsm_x4_t(bh1, smb + SM_VH + vrow * VROW + 32 + (lane >> 4) * 16);
                ldsm_x4_t(bl0, smb + SM_VL + vrow * VROW + (lane >> 4) * 16);
                ldsm_x4_t(bl1, smb + SM_VL + vrow * VROW + 32 + (lane >> 4) * 16);
                mma16816(O[mt][0], phi, bh0); mma16816(O[mt][1], phi, bh0 + 2);
                mma16816(O[mt][2], phi, bh1); mma16816(O[mt][3], phi, bh1 + 2);
                mma16816(O[mt][0], plo, bh0); mma16816(O[mt][1], plo, bh0 + 2);
                mma16816(O[mt][2], plo, bh1); mma16816(O[mt][3], plo, bh1 + 2);
                mma16816(O[mt][0], phi, bl0); mma16816(O[mt][1], phi, bl0 + 2);
                mma16816(O[mt][2], phi, bl1); mma16816(O[mt][3], phi, bl1 + 2);
            }
        }
    }

    int r = lane >> 2, c = (lane & 3) * 2;
    #pragma unroll
    for (int mt = 0; mt < 2; mt++) {
        float invA = 1.f / lst[mt][0];
        float invB = 1.f / lst[mt][1];
        int qA = wid * 32 + mt * 16 + r;
        int qB = qA + 8;
        #pragma unroll
        for (int nt = 0; nt < 4; nt++) {
            if (qA < LQ) {
                float* cp = g_ctx + ((long)e * MQ + qA * BB + b) * D + h * HD
                            + nt * 8 + c;
                *(float2*)cp = make_float2(O[mt][nt][0] * invA,
                                           O[mt][nt][1] * invA);
            }
            if (qB < LQ) {
                float* cp = g_ctx + ((long)e * MQ + qB * BB + b) * D + h * HD
                            + nt * 8 + c;
                *(float2*)cp = make_float2(O[mt][nt][2] * invB,
                                           O[mt][nt][3] * invB);
            }
        }
    }
}

// ---------------- gated combine + residual + LayerNorm ---------------------
__global__ void __launch_bounds__(256)
combine_ln(const float* __restrict__ tgt,
           const float* __restrict__ gamma,
           const float* __restrict__ beta,
           float* __restrict__ out) {
    int m = blockIdx.x;
    int k = threadIdx.x;
    float g[NE];
    #pragma unroll
    for (int e = 0; e < NE; e++) g[e] = g_gate[m*NE + e];
    float x = tgt[(long)m * D + k];
    #pragma unroll
    for (int e = 0; e < NE; e++)
        x = fmaf(g[e], g_out[(long)e * MQ * D + (long)m * D + k], x);

    __shared__ float red[16];
    float s = x, s2 = x * x;
    #pragma unroll
    for (int o = 16; o > 0; o >>= 1) {
        s  += __shfl_xor_sync(0xffffffffu, s, o);
        s2 += __shfl_xor_sync(0xffffffffu, s2, o);
    }
    int wid = k >> 5, lane = k & 31;
    if (lane == 0) { red[wid] = s; red[8 + wid] = s2; }
    __syncthreads();
    if (k < 32) {
        float a  = (k < 8) ? red[k]     : 0.f;
        float b2 = (k < 8) ? red[8 + k] : 0.f;
        #pragma unroll
        for (int o = 4; o > 0; o >>= 1) {
            a  += __shfl_xor_sync(0xffffffffu, a,  o);
            b2 += __shfl_xor_sync(0xffffffffu, b2, o);
        }
        if (k == 0) { red[0] = a; red[1] = b2; }
    }
    __syncthreads();
    float mu  = red[0] * (1.f / D);
    float var = red[1] * (1.f / D) - mu * mu;
    float r = rsqrtf(var + 1e-5f);
    out[(long)m * D + k] = (x - mu) * r * gamma[k] + beta[k];
}

// ---------------- launch ----------------------------------------------------
extern "C" void kernel_launch(void* const* d_in, const int* in_sizes, int n_in,
                              void* d_out, int out_size) {
    const float* tgt    = (const float*)d_in[0];
    const float* memory = (const float*)d_in[1];
    const float* qpos   = (const float*)d_in[2];
    const float* pos    = (const float*)d_in[3];
    const float* w_in   = (const float*)d_in[4];
    const float* b_in   = (const float*)d_in[5];
    const float* w_out  = (const float*)d_in[6];
    const float* b_out  = (const float*)d_in[7];
    const float* w_gate = (const float*)d_in[8];
    const float* b_gate = (const float*)d_in[9];
    const float* gamma  = (const float*)d_in[10];
    const float* beta   = (const float*)d_in[11];

    float *pQ, *pKV, *pCtx, *pOut;
    __half *pAq, *pAkv, *pAc, *pWq, *pWkv, *pWo;
    cudaGetSymbolAddress((void**)&pQ,   g_Q);
    cudaGetSymbolAddress((void**)&pKV,  g_KV);
    cudaGetSymbolAddress((void**)&pCtx, g_ctx);
    cudaGetSymbolAddress((void**)&pOut, g_out);
    cudaGetSymbolAddress((void**)&pAq,  g_Aq);
    cudaGetSymbolAddress((void**)&pAkv, g_Akv);
    cudaGetSymbolAddress((void**)&pAc,  g_Ac);
    cudaGetSymbolAddress((void**)&pWq,  g_Wq);
    cudaGetSymbolAddress((void**)&pWkv, g_Wkv);
    cudaGetSymbolAddress((void**)&pWo,  g_Wo);

    cudaFuncSetAttribute(gemm_mma, cudaFuncAttributeMaxDynamicSharedMemorySize, GEMM_SMEM);
    cudaFuncSetAttribute(attn_mma, cudaFuncAttributeMaxDynamicSharedMemorySize, ATT_SMEM);

    // 0: K/V activation conversion
    convert_kv<<<(MK*64 + 255)/256, 256>>>(memory, pos, pAkv, pAkv + (long)MK*KA);
    // 1: all weight conversions (single fp16)
    convert_w_all<<<(NEXP*64 + 255)/256, 256>>>(w_in, w_out, pWq, pWkv,
                                                pWkv + (long)NEXP*KW, pWo);
    // 2: Q activation conversion
    convert_act<<<(MQ*64 + 255)/256, 256>>>(tgt, qpos, pAq, MQ);

    // 3: merged K+V projection GEMM (z=0 -> K, z=1 -> V)  [profiled slot]
    gemm_mma<<<dim3(64, 10, 2), 256, GEMM_SMEM>>>(
        pAkv, pWkv, b_in, pKV, MK, NEXP,
        (long)MK*KA, (long)NEXP*KW, 256, (long)MK*NEXP, 768, 256);

    // 4: Q projection
    gemm_mma<<<dim3(7, 10, 1), 256, GEMM_SMEM>>>(pAq, pWq, b_in, pQ, MQ, NEXP,
                                                 0, 0, 0, 0, 768, 0);
    // 5: gate softmax
    gate_kernel<<<(MQ*32 + 127)/128, 128>>>(tgt, w_gate, b_gate);

    // 6: tensor-core flash attention
    attn_mma<<<dim3(NH, BB, NE), 128, ATT_SMEM>>>();

    // 7: ctx conversion
    convert_act<<<(NE*MQ*64 + 255)/256, 256>>>(pCtx, nullptr, pAc, NE*MQ);

    // 8: out projection (per expert via grid.z)
    gemm_mma<<<dim3(7, 2, 5), 256, GEMM_SMEM>>>(pAc, pWo, b_out, pOut, MQ, D,
                                                (long)MQ*KA, (long)D*KW,
                                                D, (long)MQ*D, 0, 0);

    // 9: gated combine + residual + LN
    combine_ln<<<MQ, 256>>>(tgt, gamma, beta, (float*)d_out);
}

// round 9
// speedup vs baseline: 1.6533x; 1.3898x over previous
#include <cuda_runtime.h>
#include <cuda_bf16.h>
#include <cuda_fp16.h>
#include <math.h>
#include <cstdint>

// Problem constants
#define D      256
#define NH     8
#define HD     32
#define NE     5
#define LQ     100
#define LK     1024
#define BB     16
#define MQ     (LQ*BB)      // 1600
#define MK     (LK*BB)      // 16384
#define NEXP   (NE*D)       // 1280
#define KA     256          // A: single fp16
#define KW     256          // W: single fp16
#define NCHUNK 4

// ---------------- scratch (device globals) ---------------------------------
__device__ float g_Q[MQ*NEXP];
__device__ float g_KV[2L*MK*NEXP];          // [0]=K, [1]=V
__device__ float g_gate[MQ*NE];
__device__ float g_ctx[NE*MQ*D];
__device__ float g_out[NE*MQ*D];

__device__ __half g_Aq[MQ*KA];
__device__ __half g_Akv[2L*MK*KA];          // [0]=K-act, [1]=V-act
__device__ __half g_Ac[NE*MQ*KA];
__device__ __half g_Wq[NEXP*KW];
__device__ __half g_Wkv[2L*NEXP*KW];        // [0]=Wk, [1]=Wv
__device__ __half g_Wo[NEXP*KW];

// ---------------- helpers ----------------------------------------------------
__device__ __forceinline__ uint32_t smem_u32(const void* p) {
    uint32_t a;
    asm("{ .reg .u64 t; cvta.to.shared.u64 t, %1; cvt.u32.u64 %0, t; }"
        : "=r"(a) : "l"(p));
    return a;
}

__device__ __forceinline__ uint32_t sw(uint32_t off) {
    return off ^ ((off >> 3) & 0x70);
}

__device__ __forceinline__ void cp16(uint32_t dst, const void* src, bool pred) {
    int sz = pred ? 16 : 0;
    asm volatile("cp.async.cg.shared.global [%0], [%1], 16, %2;"
                 :: "r"(dst), "l"(src), "r"(sz));
}
#define CP_COMMIT() asm volatile("cp.async.commit_group;" ::: "memory")
#define CP_WAIT2()  asm volatile("cp.async.wait_group 2;" ::: "memory")
#define CP_WAIT1()  asm volatile("cp.async.wait_group 1;" ::: "memory")
#define CP_WAIT0()  asm volatile("cp.async.wait_group 0;" ::: "memory")

__device__ __forceinline__ void ldsm_x4(uint32_t* r, uint32_t addr) {
    asm volatile("ldmatrix.sync.aligned.m8n8.x4.shared.b16 {%0,%1,%2,%3}, [%4];"
                 : "=r"(r[0]), "=r"(r[1]), "=r"(r[2]), "=r"(r[3]) : "r"(addr));
}

__device__ __forceinline__ void ldsm_x4_t(uint32_t* r, uint32_t addr) {
    asm volatile("ldmatrix.sync.aligned.m8n8.x4.trans.shared.b16 {%0,%1,%2,%3}, [%4];"
                 : "=r"(r[0]), "=r"(r[1]), "=r"(r[2]), "=r"(r[3]) : "r"(addr));
}

// fp16 MMA
__device__ __forceinline__ void mma16816h(float* d, const uint32_t* a,
                                          const uint32_t* b) {
    asm volatile(
        "mma.sync.aligned.m16n8k16.row.col.f32.f16.f16.f32 "
        "{%0,%1,%2,%3}, {%4,%5,%6,%7}, {%8,%9}, {%0,%1,%2,%3};"
        : "+f"(d[0]), "+f"(d[1]), "+f"(d[2]), "+f"(d[3])
        : "r"(a[0]), "r"(a[1]), "r"(a[2]), "r"(a[3]), "r"(b[0]), "r"(b[1]));
}

__device__ __forceinline__ uint32_t packh2(float x, float y) {
    uint32_t d;
    asm("cvt.rn.f16x2.f32 %0, %1, %2;" : "=r"(d) : "f"(y), "f"(x));
    return d;
}

__device__ __forceinline__ void splith2(float x, float y, uint32_t& hi, uint32_t& lo) {
    hi = packh2(x, y);
    __half2 h = *(__half2*)&hi;
    lo = packh2(x - __half2float(h.x), y - __half2float(h.y));
}

// ---------------- fp16 conversions (vectorized) ------------------------------
__global__ void convert_act(const float* __restrict__ a,
                            const float* __restrict__ b,
                            __half* __restrict__ out, int M) {
    int idx = blockIdx.x * blockDim.x + threadIdx.x;   // over M*64 float4s
    if (idx >= M * 64) return;
    float4 f = *(const float4*)(a + (long)idx * 4);
    if (b) {
        float4 g = *(const float4*)(b + (long)idx * 4);
        f.x += g.x; f.y += g.y; f.z += g.z; f.w += g.w;
    }
    *(uint2*)(out + (long)idx * 4) = make_uint2(packh2(f.x, f.y), packh2(f.z, f.w));
}

// fused K/V conversion: reads memory (+pos) once
__global__ void convert_kv(const float* __restrict__ mem,
                           const float* __restrict__ pos,
                           __half* __restrict__ outK,
                           __half* __restrict__ outV) {
    int idx = blockIdx.x * blockDim.x + threadIdx.x;
    if (idx >= MK * 64) return;
    float4 v = *(const float4*)(mem + (long)idx * 4);
    float4 p = *(const float4*)(pos + (long)idx * 4);
    *(uint2*)(outK + (long)idx * 4) =
        make_uint2(packh2(v.x + p.x, v.y + p.y), packh2(v.z + p.z, v.w + p.w));
    *(uint2*)(outV + (long)idx * 4) =
        make_uint2(packh2(v.x, v.y), packh2(v.z, v.w));
}

// all four weight tensors in one launch; single fp16
__global__ void convert_w_all(const float* __restrict__ w_in,
                              const float* __restrict__ w_out,
                              __half* __restrict__ oq,
                              __half* __restrict__ ok,
                              __half* __restrict__ ov,
                              __half* __restrict__ oo) {
    int idx = blockIdx.x * blockDim.x + threadIdx.x;   // over NEXP*64
    if (idx >= NEXP * 64) return;
    int n = idx >> 6, k4 = (idx & 63) << 2;
    int e = n >> 8, o = n & 255;
    long base = (long)n * KW + k4;
    __half* dsts[3] = {oq, ok, ov};
    #pragma unroll
    for (int sec = 0; sec < 3; sec++) {
        float4 f = *(const float4*)(w_in + ((long)e * 768 + sec * 256 + o) * 256 + k4);
        *(uint2*)(dsts[sec] + base) = make_uint2(packh2(f.x, f.y), packh2(f.z, f.w));
    }
    {
        float4 f = *(const float4*)(w_out + ((long)e * 256 + o) * 256 + k4);
        *(uint2*)(oo + base) = make_uint2(packh2(f.x, f.y), packh2(f.z, f.w));
    }
}

// ---------------- fp16 HMMA GEMM: 256x128 tile, 8 warps, 64x64 warp tile ----
#define TM 256
#define TN 128
#define STG 49152
#define GEMM_SMEM (3*STG)

__device__ __forceinline__ void gemm_issue(uint32_t smb, int c,
                                           const __half* A,
                                           const __half* Wb,
                                           int m0, int M, int tid) {
    uint32_t st = smb + (c % 3) * STG;
    int ko = c * 64;
    #pragma unroll
    for (int i = 0; i < 8; i++) {
        int idx = tid + i * 256, row = idx >> 3, seg = idx & 7;
        int m = m0 + row;
        cp16(st + sw(row * 128 + seg * 16),
             A + (long)m * KA + ko + seg * 8, m < M);
    }
    #pragma unroll
    for (int i = 0; i < 4; i++) {
        int idx = tid + i * 256, row = idx >> 3, seg = idx & 7;
        cp16(st + TM * 128 + sw(row * 128 + seg * 16),
             Wb + (long)row * KW + ko + seg * 8, true);
    }
    CP_COMMIT();
}

__global__ void __launch_bounds__(256)
gemm_mma(const __half* __restrict__ A, const __half* __restrict__ W,
         const float* __restrict__ bias, float* __restrict__ C,
         int M, int ldc,
         long aZ, long wZ, int bZ, long cZ, int bES, int bSO) {
    extern __shared__ char smc[];
    uint32_t smb = smem_u32(smc);
    int tid = threadIdx.x, wid = tid >> 5, lane = tid & 31;
    int z = blockIdx.z;
    A += z * aZ;
    C += z * cZ;
    int m0 = blockIdx.x * TM;
    int n0 = blockIdx.y * TN;
    const __half* Wb = W + z * wZ + (long)n0 * KW;

    int wm = wid >> 1, wn = wid & 1;   // 4x2 warp grid, 64x64 warp tile
    float acc[4][8][4];
    #pragma unroll
    for (int i = 0; i < 4; i++)
        #pragma unroll
        for (int j = 0; j < 8; j++)
            #pragma unroll
            for (int q = 0; q < 4; q++) acc[i][j][q] = 0.f;

    gemm_issue(smb, 0, A, Wb, m0, M, tid);
    gemm_issue(smb, 1, A, Wb, m0, M, tid);

    for (int c = 0; c < NCHUNK; c++) {
        if (c + 2 < NCHUNK) { gemm_issue(smb, c + 2, A, Wb, m0, M, tid); CP_WAIT2(); }
        else if (c + 1 < NCHUNK) { CP_WAIT1(); }
        else { CP_WAIT0(); }
        __syncthreads();

        uint32_t stA = smb + (c % 3) * STG;
        uint32_t stB = stA + TM * 128;
        #pragma unroll
        for (int ks = 0; ks < 4; ks++) {
            uint32_t a[4][4];
            #pragma unroll
            for (int mi = 0; mi < 4; mi++) {
                int r = wm * 64 + mi * 16 + (lane & 7) + ((lane >> 3) & 1) * 8;
                int cB = (ks * 16 + (lane >> 4) * 8) * 2;
                ldsm_x4(a[mi], stA + sw(r * 128 + cB));
            }
            uint32_t b[4][4];
            #pragma unroll
            for (int ni = 0; ni < 4; ni++) {
                int r = wn * 64 + ni * 16 + (lane & 7) + (lane >> 4) * 8;
                int cB = (ks * 16 + ((lane >> 3) & 1) * 8) * 2;
                ldsm_x4(b[ni], stB + sw(r * 128 + cB));
            }
            #pragma unroll
            for (int mi = 0; mi < 4; mi++) {
                #pragma unroll
                for (int nj = 0; nj < 8; nj++) {
                    mma16816h(acc[mi][nj], a[mi], &b[nj >> 1][(nj & 1) * 2]);
                }
            }
        }
        __syncthreads();
    }

    int tq = lane >> 2, tr = lane & 3;
    #pragma unroll
    for (int mi = 0; mi < 4; mi++) {
        #pragma unroll
        for (int nj = 0; nj < 8; nj++) {
            int gm = m0 + wm * 64 + mi * 16 + tq;
            int lc = n0 + wn * 64 + nj * 8 + tr * 2;
            int e = lc >> 8;
            int bidx = z * bZ + e * bES + bSO + (lc & 255);
            float bx = __ldg(bias + bidx);
            float by = __ldg(bias + bidx + 1);
            if (gm < M) {
                float2 o = make_float2(acc[mi][nj][0] + bx, acc[mi][nj][1] + by);
                *(float2*)(C + (long)gm * ldc + lc) = o;
            }
            if (gm + 8 < M) {
                float2 o = make_float2(acc[mi][nj][2] + bx, acc[mi][nj][3] + by);
                *(float2*)(C + (long)(gm + 8) * ldc + lc) = o;
            }
        }
    }
}

// ---------------- gate: softmax over 5 experts per token -------------------
__global__ void gate_kernel(const float* __restrict__ tgt,
                            const float* __restrict__ wg,
                            const float* __restrict__ bg) {
    int warp = (blockIdx.x * blockDim.x + threadIdx.x) >> 5;
    int lane = threadIdx.x & 31;
    if (warp >= MQ) return;
    const float* x = tgt + warp * D;
    float logit[NE];
    #pragma unroll
    for (int e = 0; e < NE; e++) {
        float s = 0.f;
        #pragma unroll
        for (int k = lane; k < D; k += 32) s = fmaf(x[k], wg[e*D + k], s);
        #pragma unroll
        for (int o = 16; o > 0; o >>= 1) s += __shfl_xor_sync(0xffffffffu, s, o);
        logit[e] = s + bg[e];
    }
    if (lane == 0) {
        float mx = logit[0];
        #pragma unroll
        for (int e = 1; e < NE; e++) mx = fmaxf(mx, logit[e]);
        float p[NE], sum = 0.f;
        #pragma unroll
        for (int e = 0; e < NE; e++) { p[e] = __expf(logit[e] - mx); sum += p[e]; }
        float inv = 1.f / sum;
        #pragma unroll
        for (int e = 0; e < NE; e++) g_gate[warp*NE + e] = p[e] * inv;
    }
}

// ---------------- tensor-core flash attention (fp16: Q 2-term, K/V 1-term) --
// Q cat row: [Qhi(32)|Qlo(32)] fp16 = 128B; K cat row: [K|K] fp16 = 128B.
// Padded row stride 144B keeps ldmatrix conflict-free. V: 32 fp16 = 64B @ 80B.
#define QROW 144
#define VROW 80
#define SM_Q  0
#define SM_K  18432
#define SM_V  36864
#define ATT_SMEM 47104

__global__ void __launch_bounds__(128) attn_mma() {
    extern __shared__ char smc[];
    uint32_t smb = smem_u32(smc);
    int h = blockIdx.x, b = blockIdx.y, e = blockIdx.z;
    int tid = threadIdx.x, wid = tid >> 5, lane = tid & 31;
    const float scale = 0.17677669529663688f;  // 1/sqrt(32)
    const float* gK = g_KV;
    const float* gV = g_KV + (long)MK * NEXP;

    // ---- load + split Q (row = tid), rows >= LQ zeroed ------------------
    {
        char* qrow = smc + SM_Q + tid * QROW;
        if (tid < LQ) {
            const float4* qp = (const float4*)(g_Q + ((long)(tid * BB + b)) * NEXP
                                               + e * D + h * HD);
            #pragma unroll
            for (int j = 0; j < 8; j++) {
                float4 f = qp[j];
                uint32_t h01, l01, h23, l23;
                splith2(f.x * scale, f.y * scale, h01, l01);
                splith2(f.z * scale, f.w * scale, h23, l23);
                *(uint2*)(qrow + j * 8)      = make_uint2(h01, h23);  // hi
                *(uint2*)(qrow + 64 + j * 8) = make_uint2(l01, l23);  // lo
            }
        } else {
            uint2 z = make_uint2(0, 0);
            #pragma unroll
            for (int j = 0; j < 16; j++)
                *(uint2*)(qrow + j * 8) = z;
        }
    }

    float mst[2][2], lst[2][2], O[2][4][4];
    #pragma unroll
    for (int mt = 0; mt < 2; mt++) {
        mst[mt][0] = -INFINITY; mst[mt][1] = -INFINITY;
        lst[mt][0] = 0.f; lst[mt][1] = 0.f;
        #pragma unroll
        for (int nt = 0; nt < 4; nt++)
            #pragma unroll
            for (int q = 0; q < 4; q++) O[mt][nt][q] = 0.f;
    }

    for (int s0 = 0; s0 < LK; s0 += 128) {
        __syncthreads();
        // ---- load K (duplicated [K|K]) and V (single fp16) ---------------
        {
            long base = ((long)((s0 + tid) * BB + b)) * NEXP + e * D + h * HD;
            const float4* kp = (const float4*)(gK + base);
            const float4* vp = (const float4*)(gV + base);
            char* krow = smc + SM_K + tid * QROW;
            char* vrow = smc + SM_V + tid * VROW;
            #pragma unroll
            for (int j = 0; j < 8; j++) {
                float4 f = kp[j];
                uint2 kv = make_uint2(packh2(f.x, f.y), packh2(f.z, f.w));
                *(uint2*)(krow + j * 8)      = kv;
                *(uint2*)(krow + 64 + j * 8) = kv;
                f = vp[j];
                *(uint2*)(vrow + j * 8) =
                    make_uint2(packh2(f.x, f.y), packh2(f.z, f.w));
            }
        }
        __syncthreads();

        #pragma unroll
        for (int mt = 0; mt < 2; mt++) {
            int m0 = wid * 32 + mt * 16;
            uint32_t aq[4][4];
            #pragma unroll
            for (int kk = 0; kk < 4; kk++)
                ldsm_x4(aq[kk], smb + SM_Q + (m0 + (lane & 15)) * QROW
                                 + kk * 32 + (lane >> 4) * 16);
            float S[16][4];
            #pragma unroll
            for (int nt = 0; nt < 16; nt++)
                #pragma unroll
                for (int q = 0; q < 4; q++) S[nt][q] = 0.f;
            #pragma unroll
            for (int ng = 0; ng < 8; ng++) {
                #pragma unroll
                for (int kk = 0; kk < 4; kk++) {
                    uint32_t bk[4];
                    ldsm_x4(bk, smb + SM_K
                            + (ng * 16 + (lane & 7) + ((lane >> 4) << 3)) * QROW
                            + kk * 32 + (((lane >> 3) & 1) << 4));
                    mma16816h(S[2 * ng],     aq[kk], bk);
                    mma16816h(S[2 * ng + 1], aq[kk], bk + 2);
                }
            }
            // ---- online softmax ------------------------------------------
            float vA = -INFINITY, vB = -INFINITY;
            #pragma unroll
            for (int nt = 0; nt < 16; nt++) {
                vA = fmaxf(vA, fmaxf(S[nt][0], S[nt][1]));
                vB = fmaxf(vB, fmaxf(S[nt][2], S[nt][3]));
            }
            vA = fmaxf(vA, __shfl_xor_sync(0xffffffffu, vA, 1));
            vA = fmaxf(vA, __shfl_xor_sync(0xffffffffu, vA, 2));
            vB = fmaxf(vB, __shfl_xor_sync(0xffffffffu, vB, 1));
            vB = fmaxf(vB, __shfl_xor_sync(0xffffffffu, vB, 2));
            float mnA = fmaxf(mst[mt][0], vA), mnB = fmaxf(mst[mt][1], vB);
            float fA = __expf(mst[mt][0] - mnA), fB = __expf(mst[mt][1] - mnB);
            mst[mt][0] = mnA; mst[mt][1] = mnB;
            float sA = 0.f, sB = 0.f;
            #pragma unroll
            for (int nt = 0; nt < 16; nt++) {
                S[nt][0] = __expf(S[nt][0] - mnA);
                S[nt][1] = __expf(S[nt][1] - mnA);
                S[nt][2] = __expf(S[nt][2] - mnB);
                S[nt][3] = __expf(S[nt][3] - mnB);
                sA += S[nt][0] + S[nt][1];
                sB += S[nt][2] + S[nt][3];
            }
            sA += __shfl_xor_sync(0xffffffffu, sA, 1);
            sA += __shfl_xor_sync(0xffffffffu, sA, 2);
            sB += __shfl_xor_sync(0xffffffffu, sB, 1);
            sB += __shfl_xor_sync(0xffffffffu, sB, 2);
            lst[mt][0] = lst[mt][0] * fA + sA;
            lst[mt][1] = lst[mt][1] * fB + sB;
            #pragma unroll
            for (int nt = 0; nt < 4; nt++) {
                O[mt][nt][0] *= fA; O[mt][nt][1] *= fA;
                O[mt][nt][2] *= fB; O[mt][nt][3] *= fB;
            }
            // ---- P @ V, single fp16 term ----------------------------------
            #pragma unroll
            for (int kt = 0; kt < 8; kt++) {
                uint32_t ph[4];
                ph[0] = packh2(S[2*kt][0],   S[2*kt][1]);
                ph[1] = packh2(S[2*kt][2],   S[2*kt][3]);
                ph[2] = packh2(S[2*kt+1][0], S[2*kt+1][1]);
                ph[3] = packh2(S[2*kt+1][2], S[2*kt+1][3]);
                uint32_t vrow = kt * 16 + (lane & 15);
                uint32_t bv0[4], bv1[4];
                ldsm_x4_t(bv0, smb + SM_V + vrow * VROW + (lane >> 4) * 16);
                ldsm_x4_t(bv1, smb + SM_V + vrow * VROW + 32 + (lane >> 4) * 16);
                mma16816h(O[mt][0], ph, bv0); mma16816h(O[mt][1], ph, bv0 + 2);
                mma16816h(O[mt][2], ph, bv1); mma16816h(O[mt][3], ph, bv1 + 2);
            }
        }
    }

    // ---- epilogue: normalize and store ctx ------------------------------
    int r = lane >> 2, c = (lane & 3) * 2;
    #pragma unroll
    for (int mt = 0; mt < 2; mt++) {
        float invA = 1.f / lst[mt][0];
        float invB = 1.f / lst[mt][1];
        int qA = wid * 32 + mt * 16 + r;
        int qB = qA + 8;
        #pragma unroll
        for (int nt = 0; nt < 4; nt++) {
            if (qA < LQ) {
                float* cp = g_ctx + ((long)e * MQ + qA * BB + b) * D + h * HD
                            + nt * 8 + c;
                *(float2*)cp = make_float2(O[mt][nt][0] * invA,
                                           O[mt][nt][1] * invA);
            }
            if (qB < LQ) {
                float* cp = g_ctx + ((long)e * MQ + qB * BB + b) * D + h * HD
                            + nt * 8 + c;
                *(float2*)cp = make_float2(O[mt][nt][2] * invB,
                                           O[mt][nt][3] * invB);
            }
        }
    }
}

// ---------------- gated combine + residual + LayerNorm ---------------------
__global__ void __launch_bounds__(256)
combine_ln(const float* __restrict__ tgt,
           const float* __restrict__ gamma,
           const float* __restrict__ beta,
           float* __restrict__ out) {
    int m = blockIdx.x;
    int k = threadIdx.x;
    float g[NE];
    #pragma unroll
    for (int e = 0; e < NE; e++) g[e] = g_gate[m*NE + e];
    float x = tgt[(long)m * D + k];
    #pragma unroll
    for (int e = 0; e < NE; e++)
        x = fmaf(g[e], g_out[(long)e * MQ * D + (long)m * D + k], x);

    __shared__ float red[16];
    float s = x, s2 = x * x;
    #pragma unroll
    for (int o = 16; o > 0; o >>= 1) {
        s  += __shfl_xor_sync(0xffffffffu, s, o);
        s2 += __shfl_xor_sync(0xffffffffu, s2, o);
    }
    int wid = k >> 5, lane = k & 31;
    if (lane == 0) { red[wid] = s; red[8 + wid] = s2; }
    __syncthreads();
    if (k < 32) {
        float a  = (k < 8) ? red[k]     : 0.f;
        float b2 = (k < 8) ? red[8 + k] : 0.f;
        #pragma unroll
        for (int o = 4; o > 0; o >>= 1) {
            a  += __shfl_xor_sync(0xffffffffu, a,  o);
            b2 += __shfl_xor_sync(0xffffffffu, b2, o);
        }
        if (k == 0) { red[0] = a; red[1] = b2; }
    }
    __syncthreads();
    float mu  = red[0] * (1.f / D);
    float var = red[1] * (1.f / D) - mu * mu;
    float r = rsqrtf(var + 1e-5f);
    out[(long)m * D + k] = (x - mu) * r * gamma[k] + beta[k];
}

// ---------------- launch ----------------------------------------------------
extern "C" void kernel_launch(void* const* d_in, const int* in_sizes, int n_in,
                              void* d_out, int out_size) {
    const float* tgt    = (const float*)d_in[0];
    const float* memory = (const float*)d_in[1];
    const float* qpos   = (const float*)d_in[2];
    const float* pos    = (const float*)d_in[3];
    const float* w_in   = (const float*)d_in[4];
    const float* b_in   = (const float*)d_in[5];
    const float* w_out  = (const float*)d_in[6];
    const float* b_out  = (const float*)d_in[7];
    const float* w_gate = (const float*)d_in[8];
    const float* b_gate = (const float*)d_in[9];
    const float* gamma  = (const float*)d_in[10];
    const float* beta   = (const float*)d_in[11];

    float *pQ, *pKV, *pCtx, *pOut;
    __half *pAq, *pAkv, *pAc, *pWq, *pWkv, *pWo;
    cudaGetSymbolAddress((void**)&pQ,   g_Q);
    cudaGetSymbolAddress((void**)&pKV,  g_KV);
    cudaGetSymbolAddress((void**)&pCtx, g_ctx);
    cudaGetSymbolAddress((void**)&pOut, g_out);
    cudaGetSymbolAddress((void**)&pAq,  g_Aq);
    cudaGetSymbolAddress((void**)&pAkv, g_Akv);
    cudaGetSymbolAddress((void**)&pAc,  g_Ac);
    cudaGetSymbolAddress((void**)&pWq,  g_Wq);
    cudaGetSymbolAddress((void**)&pWkv, g_Wkv);
    cudaGetSymbolAddress((void**)&pWo,  g_Wo);

    cudaFuncSetAttribute(gemm_mma, cudaFuncAttributeMaxDynamicSharedMemorySize, GEMM_SMEM);
    cudaFuncSetAttribute(attn_mma, cudaFuncAttributeMaxDynamicSharedMemorySize, ATT_SMEM);

    // 0: K/V activation conversion
    convert_kv<<<(MK*64 + 255)/256, 256>>>(memory, pos, pAkv, pAkv + (long)MK*KA);
    // 1: all weight conversions
    convert_w_all<<<(NEXP*64 + 255)/256, 256>>>(w_in, w_out, pWq, pWkv,
                                                pWkv + (long)NEXP*KW, pWo);
    // 2: Q activation conversion
    convert_act<<<(MQ*64 + 255)/256, 256>>>(tgt, qpos, pAq, MQ);

    // 3: merged K+V projection GEMM (z=0 -> K, z=1 -> V)  [profiled slot]
    gemm_mma<<<dim3(64, 10, 2), 256, GEMM_SMEM>>>(
        pAkv, pWkv, b_in, pKV, MK, NEXP,
        (long)MK*KA, (long)NEXP*KW, 256, (long)MK*NEXP, 768, 256);

    // 4: Q projection
    gemm_mma<<<dim3(7, 10, 1), 256, GEMM_SMEM>>>(pAq, pWq, b_in, pQ, MQ, NEXP,
                                                 0, 0, 0, 0, 768, 0);
    // 5: gate softmax
    gate_kernel<<<(MQ*32 + 127)/128, 128>>>(tgt, w_gate, b_gate);

    // 6: tensor-core flash attention
    attn_mma<<<dim3(NH, BB, NE), 128, ATT_SMEM>>>();

    // 7: ctx conversion
    convert_act<<<(NE*MQ*64 + 255)/256, 256>>>(pCtx, nullptr, pAc, NE*MQ);

    // 8: out projection (per expert via grid.z)
    gemm_mma<<<dim3(7, 2, 5), 256, GEMM_SMEM>>>(pAc, pWo, b_out, pOut, MQ, D,
                                                (long)MQ*KA, (long)D*KW,
                                                D, (long)MQ*D, 0, 0);

    // 9: gated combine + residual + LN
    combine_ln<<<MQ, 256>>>(tgt, gamma, beta, (float*)d_out);
}

// round 10
// speedup vs baseline: 2.2211x; 1.3435x over previous
#include <cuda_runtime.h>
#include <cuda_fp16.h>
#include <math.h>
#include <cstdint>

// Problem constants
#define D      256
#define NH     8
#define HD     32
#define NE     5
#define LQ     100
#define LK     1024
#define BB     16
#define MQ     (LQ*BB)      // 1600
#define MK     (LK*BB)      // 16384
#define NEXP   (NE*D)       // 1280
#define KA     256          // A: single fp16
#define KW     256          // W: single fp16
#define NCHUNK 4

// ---------------- scratch (device globals) ---------------------------------
__device__ float g_gate[MQ*NE];
__device__ float g_out[NE*MQ*D];

__device__ __half g_Qh[MQ*2*NEXP];          // Q split [hi(1280)|lo(1280)] per row
__device__ __half g_KVh[2L*MK*NEXP];        // fp16 K, V
__device__ __half g_Aq[MQ*KA];
__device__ __half g_Akv[2L*MK*KA];          // [0]=K-act, [1]=V-act
__device__ __half g_Ac[NE*MQ*KA];           // fp16 ctx (written by attention)
__device__ __half g_Wq[NEXP*KW];
__device__ __half g_Wkv[2L*NEXP*KW];        // [0]=Wk, [1]=Wv
__device__ __half g_Wo[NEXP*KW];

// ---------------- helpers ----------------------------------------------------
__device__ __forceinline__ uint32_t smem_u32(const void* p) {
    uint32_t a;
    asm("{ .reg .u64 t; cvta.to.shared.u64 t, %1; cvt.u32.u64 %0, t; }"
        : "=r"(a) : "l"(p));
    return a;
}

__device__ __forceinline__ uint32_t sw(uint32_t off) {
    return off ^ ((off >> 3) & 0x70);
}

__device__ __forceinline__ void cp16(uint32_t dst, const void* src, bool pred) {
    int sz = pred ? 16 : 0;
    asm volatile("cp.async.cg.shared.global [%0], [%1], 16, %2;"
                 :: "r"(dst), "l"(src), "r"(sz));
}
#define CP_COMMIT() asm volatile("cp.async.commit_group;" ::: "memory")
#define CP_WAIT2()  asm volatile("cp.async.wait_group 2;" ::: "memory")
#define CP_WAIT1()  asm volatile("cp.async.wait_group 1;" ::: "memory")
#define CP_WAIT0()  asm volatile("cp.async.wait_group 0;" ::: "memory")

__device__ __forceinline__ void ldsm_x4(uint32_t* r, uint32_t addr) {
    asm volatile("ldmatrix.sync.aligned.m8n8.x4.shared.b16 {%0,%1,%2,%3}, [%4];"
                 : "=r"(r[0]), "=r"(r[1]), "=r"(r[2]), "=r"(r[3]) : "r"(addr));
}

__device__ __forceinline__ void ldsm_x4_t(uint32_t* r, uint32_t addr) {
    asm volatile("ldmatrix.sync.aligned.m8n8.x4.trans.shared.b16 {%0,%1,%2,%3}, [%4];"
                 : "=r"(r[0]), "=r"(r[1]), "=r"(r[2]), "=r"(r[3]) : "r"(addr));
}

__device__ __forceinline__ void mma16816h(float* d, const uint32_t* a,
                                          const uint32_t* b) {
    asm volatile(
        "mma.sync.aligned.m16n8k16.row.col.f32.f16.f16.f32 "
        "{%0,%1,%2,%3}, {%4,%5,%6,%7}, {%8,%9}, {%0,%1,%2,%3};"
        : "+f"(d[0]), "+f"(d[1]), "+f"(d[2]), "+f"(d[3])
        : "r"(a[0]), "r"(a[1]), "r"(a[2]), "r"(a[3]), "r"(b[0]), "r"(b[1]));
}

__device__ __forceinline__ uint32_t packh2(float x, float y) {
    uint32_t d;
    asm("cvt.rn.f16x2.f32 %0, %1, %2;" : "=r"(d) : "f"(y), "f"(x));
    return d;
}

__device__ __forceinline__ void splith2(float x, float y, uint32_t& hi, uint32_t& lo) {
    hi = packh2(x, y);
    __half2 h = *(__half2*)&hi;
    lo = packh2(x - __half2float(h.x), y - __half2float(h.y));
}

// ---------------- fp16 conversions (vectorized) ------------------------------
__global__ void convert_act(const float* __restrict__ a,
                            const float* __restrict__ b,
                            __half* __restrict__ out, int M) {
    int idx = blockIdx.x * blockDim.x + threadIdx.x;   // over M*64 float4s
    if (idx >= M * 64) return;
    float4 f = *(const float4*)(a + (long)idx * 4);
    if (b) {
        float4 g = *(const float4*)(b + (long)idx * 4);
        f.x += g.x; f.y += g.y; f.z += g.z; f.w += g.w;
    }
    *(uint2*)(out + (long)idx * 4) = make_uint2(packh2(f.x, f.y), packh2(f.z, f.w));
}

__global__ void convert_kv(const float* __restrict__ mem,
                           const float* __restrict__ pos,
                           __half* __restrict__ outK,
                           __half* __restrict__ outV) {
    int idx = blockIdx.x * blockDim.x + threadIdx.x;
    if (idx >= MK * 64) return;
    float4 v = *(const float4*)(mem + (long)idx * 4);
    float4 p = *(const float4*)(pos + (long)idx * 4);
    *(uint2*)(outK + (long)idx * 4) =
        make_uint2(packh2(v.x + p.x, v.y + p.y), packh2(v.z + p.z, v.w + p.w));
    *(uint2*)(outV + (long)idx * 4) =
        make_uint2(packh2(v.x, v.y), packh2(v.z, v.w));
}

__global__ void convert_w_all(const float* __restrict__ w_in,
                              const float* __restrict__ w_out,
                              __half* __restrict__ oq,
                              __half* __restrict__ ok,
                              __half* __restrict__ ov,
                              __half* __restrict__ oo) {
    int idx = blockIdx.x * blockDim.x + threadIdx.x;   // over NEXP*64
    if (idx >= NEXP * 64) return;
    int n = idx >> 6, k4 = (idx & 63) << 2;
    int e = n >> 8, o = n & 255;
    long base = (long)n * KW + k4;
    __half* dsts[3] = {oq, ok, ov};
    #pragma unroll
    for (int sec = 0; sec < 3; sec++) {
        float4 f = *(const float4*)(w_in + ((long)e * 768 + sec * 256 + o) * 256 + k4);
        *(uint2*)(dsts[sec] + base) = make_uint2(packh2(f.x, f.y), packh2(f.z, f.w));
    }
    {
        float4 f = *(const float4*)(w_out + ((long)e * 256 + o) * 256 + k4);
        *(uint2*)(oo + base) = make_uint2(packh2(f.x, f.y), packh2(f.z, f.w));
    }
}

// ---------------- fp16 HMMA GEMM: 128x128 tile, 4 warps, 64x64 warp tile ----
// OMODE: 0 = fp32 out, 1 = fp16 out, 2 = fp16 split [hi | +NEXP lo]
#define TM 128
#define TN 128
#define STG 32768
#define GEMM_SMEM (3*STG)

__device__ __forceinline__ void gemm_issue(uint32_t smb, int c,
                                           const __half* A,
                                           const __half* Wb,
                                           int m0, int M, int tid) {
    uint32_t st = smb + (c % 3) * STG;
    int ko = c * 64;
    #pragma unroll
    for (int i = 0; i < 8; i++) {
        int idx = tid + i * 128, row = idx >> 3, seg = idx & 7;
        int m = m0 + row;
        cp16(st + sw(row * 128 + seg * 16),
             A + (long)m * KA + ko + seg * 8, m < M);
    }
    #pragma unroll
    for (int i = 0; i < 8; i++) {
        int idx = tid + i * 128, row = idx >> 3, seg = idx & 7;
        cp16(st + TM * 128 + sw(row * 128 + seg * 16),
             Wb + (long)row * KW + ko + seg * 8, true);
    }
    CP_COMMIT();
}

template <int OMODE>
__global__ void __launch_bounds__(128)
gemm_mma(const __half* __restrict__ A, const __half* __restrict__ W,
         const float* __restrict__ bias, void* __restrict__ Cv,
         int M, int ldc,
         long aZ, long wZ, int bZ, long cZ, int bES, int bSO) {
    extern __shared__ char smc[];
    uint32_t smb = smem_u32(smc);
    int tid = threadIdx.x, wid = tid >> 5, lane = tid & 31;
    int z = blockIdx.z;
    A += z * aZ;
    int m0 = blockIdx.x * TM;
    int n0 = blockIdx.y * TN;
    const __half* Wb = W + z * wZ + (long)n0 * KW;

    int wm = wid >> 1, wn = wid & 1;   // 2x2 warp grid, 64x64 warp tile
    float acc[4][8][4];
    #pragma unroll
    for (int i = 0; i < 4; i++)
        #pragma unroll
        for (int j = 0; j < 8; j++)
            #pragma unroll
            for (int q = 0; q < 4; q++) acc[i][j][q] = 0.f;

    gemm_issue(smb, 0, A, Wb, m0, M, tid);
    gemm_issue(smb, 1, A, Wb, m0, M, tid);

    for (int c = 0; c < NCHUNK; c++) {
        if (c + 2 < NCHUNK) { gemm_issue(smb, c + 2, A, Wb, m0, M, tid); CP_WAIT2(); }
        else if (c + 1 < NCHUNK) { CP_WAIT1(); }
        else { CP_WAIT0(); }
        __syncthreads();

        uint32_t stA = smb + (c % 3) * STG;
        uint32_t stB = stA + TM * 128;
        #pragma unroll
        for (int ks = 0; ks < 4; ks++) {
            uint32_t a[4][4];
            #pragma unroll
            for (int mi = 0; mi < 4; mi++) {
                int r = wm * 64 + mi * 16 + (lane & 7) + ((lane >> 3) & 1) * 8;
                int cB = (ks * 16 + (lane >> 4) * 8) * 2;
                ldsm_x4(a[mi], stA + sw(r * 128 + cB));
            }
            uint32_t b[4][4];
            #pragma unroll
            for (int ni = 0; ni < 4; ni++) {
                int r = wn * 64 + ni * 16 + (lane & 7) + (lane >> 4) * 8;
                int cB = (ks * 16 + ((lane >> 3) & 1) * 8) * 2;
                ldsm_x4(b[ni], stB + sw(r * 128 + cB));
            }
            #pragma unroll
            for (int mi = 0; mi < 4; mi++) {
                #pragma unroll
                for (int nj = 0; nj < 8; nj++) {
                    mma16816h(acc[mi][nj], a[mi], &b[nj >> 1][(nj & 1) * 2]);
                }
            }
        }
        __syncthreads();
    }

    int tq = lane >> 2, tr = lane & 3;
    #pragma unroll
    for (int mi = 0; mi < 4; mi++) {
        #pragma unroll
        for (int nj = 0; nj < 8; nj++) {
            int gm = m0 + wm * 64 + mi * 16 + tq;
            int lc = n0 + wn * 64 + nj * 8 + tr * 2;
            int e = lc >> 8;
            int bidx = z * bZ + e * bES + bSO + (lc & 255);
            float bx = __ldg(bias + bidx);
            float by = __ldg(bias + bidx + 1);
            #pragma unroll
            for (int half_ : {0, 1}) {
                int gr = gm + half_ * 8;
                if (gr >= M) continue;
                float ox = acc[mi][nj][half_ * 2 + 0] + bx;
                float oy = acc[mi][nj][half_ * 2 + 1] + by;
                if (OMODE == 0) {
                    float* C = (float*)Cv + z * cZ;
                    *(float2*)(C + (long)gr * ldc + lc) = make_float2(ox, oy);
                } else if (OMODE == 1) {
                    __half* C = (__half*)Cv + z * cZ;
                    *(uint32_t*)(C + (long)gr * ldc + lc) = packh2(ox, oy);
                } else {
                    __half* C = (__half*)Cv + z * cZ;
                    uint32_t hi, lo;
                    splith2(ox, oy, hi, lo);
                    *(uint32_t*)(C + (long)gr * ldc + lc)        = hi;
                    *(uint32_t*)(C + (long)gr * ldc + NEXP + lc) = lo;
                }
            }
        }
    }
}

// ---------------- gate: softmax over 5 experts per token -------------------
__global__ void gate_kernel(const float* __restrict__ tgt,
                            const float* __restrict__ wg,
                            const float* __restrict__ bg) {
    int warp = (blockIdx.x * blockDim.x + threadIdx.x) >> 5;
    int lane = threadIdx.x & 31;
    if (warp >= MQ) return;
    const float* x = tgt + warp * D;
    float logit[NE];
    #pragma unroll
    for (int e = 0; e < NE; e++) {
        float s = 0.f;
        #pragma unroll
        for (int k = lane; k < D; k += 32) s = fmaf(x[k], wg[e*D + k], s);
        #pragma unroll
        for (int o = 16; o > 0; o >>= 1) s += __shfl_xor_sync(0xffffffffu, s, o);
        logit[e] = s + bg[e];
    }
    if (lane == 0) {
        float mx = logit[0];
        #pragma unroll
        for (int e = 1; e < NE; e++) mx = fmaxf(mx, logit[e]);
        float p[NE], sum = 0.f;
        #pragma unroll
        for (int e = 0; e < NE; e++) { p[e] = __expf(logit[e] - mx); sum += p[e]; }
        float inv = 1.f / sum;
        #pragma unroll
        for (int e = 0; e < NE; e++) g_gate[warp*NE + e] = p[e] * inv;
    }
}

// ---------------- tensor-core flash attention (fp16 operands from GEMMs) ----
// Q smem row: [Qhi(32)|Qlo(32)] fp16 = 128B; K row: [K|K] = 128B (stride 144).
// V: 32 fp16 = 64B (stride 80). Scale applied to scores post-MMA in fp32.
#define QROW 144
#define VROW 80
#define SM_Q  0
#define SM_K  18432
#define SM_V  36864
#define ATT_SMEM 47104

__global__ void __launch_bounds__(128) attn_mma() {
    extern __shared__ char smc[];
    uint32_t smb = smem_u32(smc);
    int h = blockIdx.x, b = blockIdx.y, e = blockIdx.z;
    int tid = threadIdx.x, wid = tid >> 5, lane = tid & 31;
    const float scale = 0.17677669529663688f;  // 1/sqrt(32)
    const __half* gK = g_KVh;
    const __half* gV = g_KVh + (long)MK * NEXP;

    // ---- copy pre-split Q (row = tid), rows >= LQ zeroed ----------------
    {
        char* qrow = smc + SM_Q + tid * QROW;
        if (tid < LQ) {
            long base = (long)(tid * BB + b) * (2 * NEXP) + e * D + h * HD;
            const uint4* qh = (const uint4*)(g_Qh + base);
            const uint4* ql = (const uint4*)(g_Qh + base + NEXP);
            #pragma unroll
            for (int i = 0; i < 4; i++) {
                *(uint4*)(qrow + i * 16)      = qh[i];
                *(uint4*)(qrow + 64 + i * 16) = ql[i];
            }
        } else {
            uint4 z = make_uint4(0, 0, 0, 0);
            #pragma unroll
            for (int i = 0; i < 8; i++)
                *(uint4*)(qrow + i * 16) = z;
        }
    }

    float mst[2][2], lst[2][2], O[2][4][4];
    #pragma unroll
    for (int mt = 0; mt < 2; mt++) {
        mst[mt][0] = -INFINITY; mst[mt][1] = -INFINITY;
        lst[mt][0] = 0.f; lst[mt][1] = 0.f;
        #pragma unroll
        for (int nt = 0; nt < 4; nt++)
            #pragma unroll
            for (int q = 0; q < 4; q++) O[mt][nt][q] = 0.f;
    }

    for (int s0 = 0; s0 < LK; s0 += 128) {
        __syncthreads();
        // ---- copy K (duplicated [K|K]) and V, pure uint4 moves ------------
        {
            long base = (long)((s0 + tid) * BB + b) * NEXP + e * D + h * HD;
            const uint4* kp = (const uint4*)(gK + base);
            const uint4* vp = (const uint4*)(gV + base);
            char* krow = smc + SM_K + tid * QROW;
            char* vrow = smc + SM_V + tid * VROW;
            #pragma unroll
            for (int i = 0; i < 4; i++) {
                uint4 kv = kp[i];
                *(uint4*)(krow + i * 16)      = kv;
                *(uint4*)(krow + 64 + i * 16) = kv;
                *(uint4*)(vrow + i * 16)      = vp[i];
            }
        }
        __syncthreads();

        #pragma unroll
        for (int mt = 0; mt < 2; mt++) {
            int m0 = wid * 32 + mt * 16;
            uint32_t aq[4][4];
            #pragma unroll
            for (int kk = 0; kk < 4; kk++)
                ldsm_x4(aq[kk], smb + SM_Q + (m0 + (lane & 15)) * QROW
                                 + kk * 32 + (lane >> 4) * 16);
            float S[16][4];
            #pragma unroll
            for (int nt = 0; nt < 16; nt++)
                #pragma unroll
                for (int q = 0; q < 4; q++) S[nt][q] = 0.f;
            #pragma unroll
            for (int ng = 0; ng < 8; ng++) {
                #pragma unroll
                for (int kk = 0; kk < 4; kk++) {
                    uint32_t bk[4];
                    ldsm_x4(bk, smb + SM_K
                            + (ng * 16 + (lane & 7) + ((lane >> 4) << 3)) * QROW
                            + kk * 32 + (((lane >> 3) & 1) << 4));
                    mma16816h(S[2 * ng],     aq[kk], bk);
                    mma16816h(S[2 * ng + 1], aq[kk], bk + 2);
                }
            }
            // scale scores (Q was stored unscaled)
            #pragma unroll
            for (int nt = 0; nt < 16; nt++) {
                S[nt][0] *= scale; S[nt][1] *= scale;
                S[nt][2] *= scale; S[nt][3] *= scale;
            }
            // ---- online softmax ------------------------------------------
            float vA = -INFINITY, vB = -INFINITY;
            #pragma unroll
            for (int nt = 0; nt < 16; nt++) {
                vA = fmaxf(vA, fmaxf(S[nt][0], S[nt][1]));
                vB = fmaxf(vB, fmaxf(S[nt][2], S[nt][3]));
            }
            vA = fmaxf(vA, __shfl_xor_sync(0xffffffffu, vA, 1));
            vA = fmaxf(vA, __shfl_xor_sync(0xffffffffu, vA, 2));
            vB = fmaxf(vB, __shfl_xor_sync(0xffffffffu, vB, 1));
            vB = fmaxf(vB, __shfl_xor_sync(0xffffffffu, vB, 2));
            float mnA = fmaxf(mst[mt][0], vA), mnB = fmaxf(mst[mt][1], vB);
            float fA = __expf(mst[mt][0] - mnA), fB = __expf(mst[mt][1] - mnB);
            mst[mt][0] = mnA; mst[mt][1] = mnB;
            float sA = 0.f, sB = 0.f;
            #pragma unroll
            for (int nt = 0; nt < 16; nt++) {
                S[nt][0] = __expf(S[nt][0] - mnA);
                S[nt][1] = __expf(S[nt][1] - mnA);
                S[nt][2] = __expf(S[nt][2] - mnB);
                S[nt][3] = __expf(S[nt][3] - mnB);
                sA += S[nt][0] + S[nt][1];
                sB += S[nt][2] + S[nt][3];
            }
            sA += __shfl_xor_sync(0xffffffffu, sA, 1);
            sA += __shfl_xor_sync(0xffffffffu, sA, 2);
            sB += __shfl_xor_sync(0xffffffffu, sB, 1);
            sB += __shfl_xor_sync(0xffffffffu, sB, 2);
            lst[mt][0] = lst[mt][0] * fA + sA;
            lst[mt][1] = lst[mt][1] * fB + sB;
            #pragma unroll
            for (int nt = 0; nt < 4; nt++) {
                O[mt][nt][0] *= fA; O[mt][nt][1] *= fA;
                O[mt][nt][2] *= fB; O[mt][nt][3] *= fB;
            }
            // ---- P @ V, single fp16 term ----------------------------------
            #pragma unroll
            for (int kt = 0; kt < 8; kt++) {
                uint32_t ph[4];
                ph[0] = packh2(S[2*kt][0],   S[2*kt][1]);
                ph[1] = packh2(S[2*kt][2],   S[2*kt][3]);
                ph[2] = packh2(S[2*kt+1][0], S[2*kt+1][1]);
                ph[3] = packh2(S[2*kt+1][2], S[2*kt+1][3]);
                uint32_t vrow = kt * 16 + (lane & 15);
                uint32_t bv0[4], bv1[4];
                ldsm_x4_t(bv0, smb + SM_V + vrow * VROW + (lane >> 4) * 16);
                ldsm_x4_t(bv1, smb + SM_V + vrow * VROW + 32 + (lane >> 4) * 16);
                mma16816h(O[mt][0], ph, bv0); mma16816h(O[mt][1], ph, bv0 + 2);
                mma16816h(O[mt][2], ph, bv1); mma16816h(O[mt][3], ph, bv1 + 2);
            }
        }
    }

    // ---- epilogue: normalize, write fp16 ctx directly (out-proj A op) ----
    int r = lane >> 2, c = (lane & 3) * 2;
    #pragma unroll
    for (int mt = 0; mt < 2; mt++) {
        float invA = 1.f / lst[mt][0];
        float invB = 1.f / lst[mt][1];
        int qA = wid * 32 + mt * 16 + r;
        int qB = qA + 8;
        #pragma unroll
        for (int nt = 0; nt < 4; nt++) {
            if (qA < LQ) {
                long ci = ((long)e * MQ + qA * BB + b) * D + h * HD + nt * 8 + c;
                *(uint32_t*)(g_Ac + ci) = packh2(O[mt][nt][0] * invA,
                                                 O[mt][nt][1] * invA);
            }
            if (qB < LQ) {
                long ci = ((long)e * MQ + qB * BB + b) * D + h * HD + nt * 8 + c;
                *(uint32_t*)(g_Ac + ci) = packh2(O[mt][nt][2] * invB,
                                                 O[mt][nt][3] * invB);
            }
        }
    }
}

// ---------------- gated combine + residual + LayerNorm ---------------------
__global__ void __launch_bounds__(256)
combine_ln(const float* __restrict__ tgt,
           const float* __restrict__ gamma,
           const float* __restrict__ beta,
           float* __restrict__ out) {
    int m = blockIdx.x;
    int k = threadIdx.x;
    float g[NE];
    #pragma unroll
    for (int e = 0; e < NE; e++) g[e] = g_gate[m*NE + e];
    float x = tgt[(long)m * D + k];
    #pragma unroll
    for (int e = 0; e < NE; e++)
        x = fmaf(g[e], g_out[(long)e * MQ * D + (long)m * D + k], x);

    __shared__ float red[16];
    float s = x, s2 = x * x;
    #pragma unroll
    for (int o = 16; o > 0; o >>= 1) {
        s  += __shfl_xor_sync(0xffffffffu, s, o);
        s2 += __shfl_xor_sync(0xffffffffu, s2, o);
    }
    int wid = k >> 5, lane = k & 31;
    if (lane == 0) { red[wid] = s; red[8 + wid] = s2; }
    __syncthreads();
    if (k < 32) {
        float a  = (k < 8) ? red[k]     : 0.f;
        float b2 = (k < 8) ? red[8 + k] : 0.f;
        #pragma unroll
        for (int o = 4; o > 0; o >>= 1) {
            a  += __shfl_xor_sync(0xffffffffu, a,  o);
            b2 += __shfl_xor_sync(0xffffffffu, b2, o);
        }
        if (k == 0) { red[0] = a; red[1] = b2; }
    }
    __syncthreads();
    float mu  = red[0] * (1.f / D);
    float var = red[1] * (1.f / D) - mu * mu;
    float r = rsqrtf(var + 1e-5f);
    out[(long)m * D + k] = (x - mu) * r * gamma[k] + beta[k];
}

// ---------------- launch ----------------------------------------------------
extern "C" void kernel_launch(void* const* d_in, const int* in_sizes, int n_in,
                              void* d_out, int out_size) {
    const float* tgt    = (const float*)d_in[0];
    const float* memory = (const float*)d_in[1];
    const float* qpos   = (const float*)d_in[2];
    const float* pos    = (const float*)d_in[3];
    const float* w_in   = (const float*)d_in[4];
    const float* b_in   = (const float*)d_in[5];
    const float* w_out  = (const float*)d_in[6];
    const float* b_out  = (const float*)d_in[7];
    const float* w_gate = (const float*)d_in[8];
    const float* b_gate = (const float*)d_in[9];
    const float* gamma  = (const float*)d_in[10];
    const float* beta   = (const float*)d_in[11];

    float *pOut;
    __half *pQh, *pKVh, *pAq, *pAkv, *pAc, *pWq, *pWkv, *pWo;
    cudaGetSymbolAddress((void**)&pOut, g_out);
    cudaGetSymbolAddress((void**)&pQh,  g_Qh);
    cudaGetSymbolAddress((void**)&pKVh, g_KVh);
    cudaGetSymbolAddress((void**)&pAq,  g_Aq);
    cudaGetSymbolAddress((void**)&pAkv, g_Akv);
    cudaGetSymbolAddress((void**)&pAc,  g_Ac);
    cudaGetSymbolAddress((void**)&pWq,  g_Wq);
    cudaGetSymbolAddress((void**)&pWkv, g_Wkv);
    cudaGetSymbolAddress((void**)&pWo,  g_Wo);

    cudaFuncSetAttribute(gemm_mma<0>, cudaFuncAttributeMaxDynamicSharedMemorySize, GEMM_SMEM);
    cudaFuncSetAttribute(gemm_mma<1>, cudaFuncAttributeMaxDynamicSharedMemorySize, GEMM_SMEM);
    cudaFuncSetAttribute(gemm_mma<2>, cudaFuncAttributeMaxDynamicSharedMemorySize, GEMM_SMEM);
    cudaFuncSetAttribute(attn_mma, cudaFuncAttributeMaxDynamicSharedMemorySize, ATT_SMEM);

    // 0-2: operand conversions
    convert_kv<<<(MK*64 + 255)/256, 256>>>(memory, pos, pAkv, pAkv + (long)MK*KA);
    convert_w_all<<<(NEXP*64 + 255)/256, 256>>>(w_in, w_out, pWq, pWkv,
                                                pWkv + (long)NEXP*KW, pWo);
    convert_act<<<(MQ*64 + 255)/256, 256>>>(tgt, qpos, pAq, MQ);

    // 3: merged K+V projection GEMM, fp16 out (z=0 -> K, z=1 -> V) [profiled]
    gemm_mma<1><<<dim3(128, 10, 2), 128, GEMM_SMEM>>>(
        pAkv, pWkv, b_in, pKVh, MK, NEXP,
        (long)MK*KA, (long)NEXP*KW, 256, (long)MK*NEXP, 768, 256);

    // 4: Q projection, fp16 split out [hi|lo]
    gemm_mma<2><<<dim3(13, 10, 1), 128, GEMM_SMEM>>>(
        pAq, pWq, b_in, pQh, MQ, 2*NEXP, 0, 0, 0, 0, 768, 0);

    // 5: gate softmax
    gate_kernel<<<(MQ*32 + 127)/128, 128>>>(tgt, w_gate, b_gate);

    // 6: tensor-core flash attention (writes fp16 ctx into g_Ac)
    attn_mma<<<dim3(NH, BB, NE), 128, ATT_SMEM>>>();

    // 7: out projection, fp32 out (per expert via grid.z)
    gemm_mma<0><<<dim3(13, 2, 5), 128, GEMM_SMEM>>>(
        pAc, pWo, b_out, pOut, MQ, D,
        (long)MQ*KA, (long)D*KW, D, (long)MQ*D, 0, 0);

    // 8: gated combine + residual + LN
    combine_ln<<<MQ, 256>>>(tgt, gamma, beta, (float*)d_out);
}

// round 11
// speedup vs baseline: 2.5438x; 1.1453x over previous
#include <cuda_runtime.h>
#include <cuda_fp16.h>
#include <math.h>
#include <cstdint>

// Problem constants
#define D      256
#define NH     8
#define HD     32
#define NE     5
#define LQ     100
#define LK     1024
#define BB     16
#define MQ     (LQ*BB)      // 1600
#define MK     (LK*BB)      // 16384
#define NEXP   (NE*D)       // 1280
#define KA     256          // A: single fp16
#define KW     256          // W: single fp16
#define NCHUNK 4

// ---------------- scratch (device globals) ---------------------------------
__device__ float g_gate[MQ*NE];
__device__ float g_out[NE*MQ*D];

__device__ __half g_Qh[MQ*NEXP];            // fp16 Q (unscaled)
__device__ __half g_KVh[2L*MK*NEXP];        // fp16 K, V
__device__ __half g_Aq[MQ*KA];
__device__ __half g_Akv[2L*MK*KA];          // [0]=K-act, [1]=V-act
__device__ __half g_Ac[NE*MQ*KA];           // fp16 ctx (written by attention)
__device__ __half g_Wq[NEXP*KW];
__device__ __half g_Wkv[2L*NEXP*KW];        // [0]=Wk, [1]=Wv
__device__ __half g_Wo[NEXP*KW];

// ---------------- helpers ----------------------------------------------------
__device__ __forceinline__ uint32_t smem_u32(const void* p) {
    uint32_t a;
    asm("{ .reg .u64 t; cvta.to.shared.u64 t, %1; cvt.u32.u64 %0, t; }"
        : "=r"(a) : "l"(p));
    return a;
}

__device__ __forceinline__ uint32_t sw(uint32_t off) {
    return off ^ ((off >> 3) & 0x70);
}

__device__ __forceinline__ void cp16(uint32_t dst, const void* src, bool pred) {
    int sz = pred ? 16 : 0;
    asm volatile("cp.async.cg.shared.global [%0], [%1], 16, %2;"
                 :: "r"(dst), "l"(src), "r"(sz));
}
#define CP_COMMIT() asm volatile("cp.async.commit_group;" ::: "memory")
#define CP_WAIT2()  asm volatile("cp.async.wait_group 2;" ::: "memory")
#define CP_WAIT1()  asm volatile("cp.async.wait_group 1;" ::: "memory")
#define CP_WAIT0()  asm volatile("cp.async.wait_group 0;" ::: "memory")

__device__ __forceinline__ void ldsm_x4(uint32_t* r, uint32_t addr) {
    asm volatile("ldmatrix.sync.aligned.m8n8.x4.shared.b16 {%0,%1,%2,%3}, [%4];"
                 : "=r"(r[0]), "=r"(r[1]), "=r"(r[2]), "=r"(r[3]) : "r"(addr));
}

__device__ __forceinline__ void ldsm_x4_t(uint32_t* r, uint32_t addr) {
    asm volatile("ldmatrix.sync.aligned.m8n8.x4.trans.shared.b16 {%0,%1,%2,%3}, [%4];"
                 : "=r"(r[0]), "=r"(r[1]), "=r"(r[2]), "=r"(r[3]) : "r"(addr));
}

__device__ __forceinline__ void mma16816h(float* d, const uint32_t* a,
                                          const uint32_t* b) {
    asm volatile(
        "mma.sync.aligned.m16n8k16.row.col.f32.f16.f16.f32 "
        "{%0,%1,%2,%3}, {%4,%5,%6,%7}, {%8,%9}, {%0,%1,%2,%3};"
        : "+f"(d[0]), "+f"(d[1]), "+f"(d[2]), "+f"(d[3])
        : "r"(a[0]), "r"(a[1]), "r"(a[2]), "r"(a[3]), "r"(b[0]), "r"(b[1]));
}

__device__ __forceinline__ uint32_t packh2(float x, float y) {
    uint32_t d;
    asm("cvt.rn.f16x2.f32 %0, %1, %2;" : "=r"(d) : "f"(y), "f"(x));
    return d;
}

// ---------------- fp16 conversions (vectorized) ------------------------------
__global__ void convert_act(const float* __restrict__ a,
                            const float* __restrict__ b,
                            __half* __restrict__ out, int M) {
    int idx = blockIdx.x * blockDim.x + threadIdx.x;   // over M*64 float4s
    if (idx >= M * 64) return;
    float4 f = *(const float4*)(a + (long)idx * 4);
    if (b) {
        float4 g = *(const float4*)(b + (long)idx * 4);
        f.x += g.x; f.y += g.y; f.z += g.z; f.w += g.w;
    }
    *(uint2*)(out + (long)idx * 4) = make_uint2(packh2(f.x, f.y), packh2(f.z, f.w));
}

__global__ void convert_kv(const float* __restrict__ mem,
                           const float* __restrict__ pos,
                           __half* __restrict__ outK,
                           __half* __restrict__ outV) {
    int idx = blockIdx.x * blockDim.x + threadIdx.x;
    if (idx >= MK * 64) return;
    float4 v = *(const float4*)(mem + (long)idx * 4);
    float4 p = *(const float4*)(pos + (long)idx * 4);
    *(uint2*)(outK + (long)idx * 4) =
        make_uint2(packh2(v.x + p.x, v.y + p.y), packh2(v.z + p.z, v.w + p.w));
    *(uint2*)(outV + (long)idx * 4) =
        make_uint2(packh2(v.x, v.y), packh2(v.z, v.w));
}

__global__ void convert_w_all(const float* __restrict__ w_in,
                              const float* __restrict__ w_out,
                              __half* __restrict__ oq,
                              __half* __restrict__ ok,
                              __half* __restrict__ ov,
                              __half* __restrict__ oo) {
    int idx = blockIdx.x * blockDim.x + threadIdx.x;   // over NEXP*64
    if (idx >= NEXP * 64) return;
    int n = idx >> 6, k4 = (idx & 63) << 2;
    int e = n >> 8, o = n & 255;
    long base = (long)n * KW + k4;
    __half* dsts[3] = {oq, ok, ov};
    #pragma unroll
    for (int sec = 0; sec < 3; sec++) {
        float4 f = *(const float4*)(w_in + ((long)e * 768 + sec * 256 + o) * 256 + k4);
        *(uint2*)(dsts[sec] + base) = make_uint2(packh2(f.x, f.y), packh2(f.z, f.w));
    }
    {
        float4 f = *(const float4*)(w_out + ((long)e * 256 + o) * 256 + k4);
        *(uint2*)(oo + base) = make_uint2(packh2(f.x, f.y), packh2(f.z, f.w));
    }
}

// ---------------- fp16 HMMA GEMM: 128x128 tile, 4 warps, 64x64 warp tile ----
// OMODE: 0 = fp32 out, 1 = fp16 out
#define TM 128
#define TN 128
#define STG 32768
#define GEMM_SMEM (3*STG)

__device__ __forceinline__ void gemm_issue(uint32_t smb, int c,
                                           const __half* A,
                                           const __half* Wb,
                                           int m0, int M, int tid) {
    uint32_t st = smb + (c % 3) * STG;
    int ko = c * 64;
    #pragma unroll
    for (int i = 0; i < 8; i++) {
        int idx = tid + i * 128, row = idx >> 3, seg = idx & 7;
        int m = m0 + row;
        cp16(st + sw(row * 128 + seg * 16),
             A + (long)m * KA + ko + seg * 8, m < M);
    }
    #pragma unroll
    for (int i = 0; i < 8; i++) {
        int idx = tid + i * 128, row = idx >> 3, seg = idx & 7;
        cp16(st + TM * 128 + sw(row * 128 + seg * 16),
             Wb + (long)row * KW + ko + seg * 8, true);
    }
    CP_COMMIT();
}

template <int OMODE>
__global__ void __launch_bounds__(128)
gemm_mma(const __half* __restrict__ A, const __half* __restrict__ W,
         const float* __restrict__ bias, void* __restrict__ Cv,
         int M, int ldc,
         long aZ, long wZ, int bZ, long cZ, int bES, int bSO) {
    extern __shared__ char smc[];
    uint32_t smb = smem_u32(smc);
    int tid = threadIdx.x, wid = tid >> 5, lane = tid & 31;
    int z = blockIdx.z;
    A += z * aZ;
    int m0 = blockIdx.x * TM;
    int n0 = blockIdx.y * TN;
    const __half* Wb = W + z * wZ + (long)n0 * KW;

    int wm = wid >> 1, wn = wid & 1;   // 2x2 warp grid, 64x64 warp tile
    float acc[4][8][4];
    #pragma unroll
    for (int i = 0; i < 4; i++)
        #pragma unroll
        for (int j = 0; j < 8; j++)
            #pragma unroll
            for (int q = 0; q < 4; q++) acc[i][j][q] = 0.f;

    gemm_issue(smb, 0, A, Wb, m0, M, tid);
    gemm_issue(smb, 1, A, Wb, m0, M, tid);

    for (int c = 0; c < NCHUNK; c++) {
        if (c + 2 < NCHUNK) { gemm_issue(smb, c + 2, A, Wb, m0, M, tid); CP_WAIT2(); }
        else if (c + 1 < NCHUNK) { CP_WAIT1(); }
        else { CP_WAIT0(); }
        __syncthreads();

        uint32_t stA = smb + (c % 3) * STG;
        uint32_t stB = stA + TM * 128;
        #pragma unroll
        for (int ks = 0; ks < 4; ks++) {
            uint32_t a[4][4];
            #pragma unroll
            for (int mi = 0; mi < 4; mi++) {
                int r = wm * 64 + mi * 16 + (lane & 7) + ((lane >> 3) & 1) * 8;
                int cB = (ks * 16 + (lane >> 4) * 8) * 2;
                ldsm_x4(a[mi], stA + sw(r * 128 + cB));
            }
            uint32_t b[4][4];
            #pragma unroll
            for (int ni = 0; ni < 4; ni++) {
                int r = wn * 64 + ni * 16 + (lane & 7) + (lane >> 4) * 8;
                int cB = (ks * 16 + ((lane >> 3) & 1) * 8) * 2;
                ldsm_x4(b[ni], stB + sw(r * 128 + cB));
            }
            #pragma unroll
            for (int mi = 0; mi < 4; mi++) {
                #pragma unroll
                for (int nj = 0; nj < 8; nj++) {
                    mma16816h(acc[mi][nj], a[mi], &b[nj >> 1][(nj & 1) * 2]);
                }
            }
        }
        __syncthreads();
    }

    int tq = lane >> 2, tr = lane & 3;
    #pragma unroll
    for (int mi = 0; mi < 4; mi++) {
        #pragma unroll
        for (int nj = 0; nj < 8; nj++) {
            int gm = m0 + wm * 64 + mi * 16 + tq;
            int lc = n0 + wn * 64 + nj * 8 + tr * 2;
            int e = lc >> 8;
            int bidx = z * bZ + e * bES + bSO + (lc & 255);
            float bx = __ldg(bias + bidx);
            float by = __ldg(bias + bidx + 1);
            #pragma unroll
            for (int half_ : {0, 1}) {
                int gr = gm + half_ * 8;
                if (gr >= M) continue;
                float ox = acc[mi][nj][half_ * 2 + 0] + bx;
                float oy = acc[mi][nj][half_ * 2 + 1] + by;
                if (OMODE == 0) {
                    float* C = (float*)Cv + z * cZ;
                    *(float2*)(C + (long)gr * ldc + lc) = make_float2(ox, oy);
                } else {
                    __half* C = (__half*)Cv + z * cZ;
                    *(uint32_t*)(C + (long)gr * ldc + lc) = packh2(ox, oy);
                }
            }
        }
    }
}

// ---------------- gate: softmax over 5 experts per token -------------------
__global__ void gate_kernel(const float* __restrict__ tgt,
                            const float* __restrict__ wg,
                            const float* __restrict__ bg) {
    int warp = (blockIdx.x * blockDim.x + threadIdx.x) >> 5;
    int lane = threadIdx.x & 31;
    if (warp >= MQ) return;
    const float* x = tgt + warp * D;
    float logit[NE];
    #pragma unroll
    for (int e = 0; e < NE; e++) {
        float s = 0.f;
        #pragma unroll
        for (int k = lane; k < D; k += 32) s = fmaf(x[k], wg[e*D + k], s);
        #pragma unroll
        for (int o = 16; o > 0; o >>= 1) s += __shfl_xor_sync(0xffffffffu, s, o);
        logit[e] = s + bg[e];
    }
    if (lane == 0) {
        float mx = logit[0];
        #pragma unroll
        for (int e = 1; e < NE; e++) mx = fmaxf(mx, logit[e]);
        float p[NE], sum = 0.f;
        #pragma unroll
        for (int e = 0; e < NE; e++) { p[e] = __expf(logit[e] - mx); sum += p[e]; }
        float inv = 1.f / sum;
        #pragma unroll
        for (int e = 0; e < NE; e++) g_gate[warp*NE + e] = p[e] * inv;
    }
}

// ---------------- tensor-core flash attention (all single fp16) ------------
// Q/K/V rows: 32 fp16 = 64B, stride 80B (conflict-free for ldsm/ldsm_t).
// Scale applied to scores post-MMA in fp32.
#define AROW 80
#define SM_Q  0
#define SM_K  10240
#define SM_V  20480
#define ATT_SMEM 30720

__global__ void __launch_bounds__(128) attn_mma() {
    extern __shared__ char smc[];
    uint32_t smb = smem_u32(smc);
    int h = blockIdx.x, b = blockIdx.y, e = blockIdx.z;
    int tid = threadIdx.x, wid = tid >> 5, lane = tid & 31;
    const float scale = 0.17677669529663688f;  // 1/sqrt(32)
    const __half* gK = g_KVh;
    const __half* gV = g_KVh + (long)MK * NEXP;

    // ---- copy Q (row = tid), rows >= LQ zeroed --------------------------
    {
        char* qrow = smc + SM_Q + tid * AROW;
        if (tid < LQ) {
            const uint4* qp = (const uint4*)(g_Qh +
                (long)(tid * BB + b) * NEXP + e * D + h * HD);
            #pragma unroll
            for (int i = 0; i < 4; i++)
                *(uint4*)(qrow + i * 16) = qp[i];
        } else {
            uint4 z = make_uint4(0, 0, 0, 0);
            #pragma unroll
            for (int i = 0; i < 4; i++)
                *(uint4*)(qrow + i * 16) = z;
        }
    }

    float mst[2][2], lst[2][2], O[2][4][4];
    #pragma unroll
    for (int mt = 0; mt < 2; mt++) {
        mst[mt][0] = -INFINITY; mst[mt][1] = -INFINITY;
        lst[mt][0] = 0.f; lst[mt][1] = 0.f;
        #pragma unroll
        for (int nt = 0; nt < 4; nt++)
            #pragma unroll
            for (int q = 0; q < 4; q++) O[mt][nt][q] = 0.f;
    }

    for (int s0 = 0; s0 < LK; s0 += 128) {
        __syncthreads();
        // ---- copy K and V, pure uint4 moves -------------------------------
        {
            long base = (long)((s0 + tid) * BB + b) * NEXP + e * D + h * HD;
            const uint4* kp = (const uint4*)(gK + base);
            const uint4* vp = (const uint4*)(gV + base);
            char* krow = smc + SM_K + tid * AROW;
            char* vrow = smc + SM_V + tid * AROW;
            #pragma unroll
            for (int i = 0; i < 4; i++) {
                *(uint4*)(krow + i * 16) = kp[i];
                *(uint4*)(vrow + i * 16) = vp[i];
            }
        }
        __syncthreads();

        #pragma unroll
        for (int mt = 0; mt < 2; mt++) {
            int m0 = wid * 32 + mt * 16;
            uint32_t aq[2][4];
            #pragma unroll
            for (int kk = 0; kk < 2; kk++)
                ldsm_x4(aq[kk], smb + SM_Q + (m0 + (lane & 15)) * AROW
                                 + kk * 32 + (lane >> 4) * 16);
            float S[16][4];
            #pragma unroll
            for (int nt = 0; nt < 16; nt++)
                #pragma unroll
                for (int q = 0; q < 4; q++) S[nt][q] = 0.f;
            #pragma unroll
            for (int ng = 0; ng < 8; ng++) {
                #pragma unroll
                for (int kk = 0; kk < 2; kk++) {
                    uint32_t bk[4];
                    ldsm_x4(bk, smb + SM_K
                            + (ng * 16 + (lane & 7) + ((lane >> 4) << 3)) * AROW
                            + kk * 32 + (((lane >> 3) & 1) << 4));
                    mma16816h(S[2 * ng],     aq[kk], bk);
                    mma16816h(S[2 * ng + 1], aq[kk], bk + 2);
                }
            }
            // scale scores (Q stored unscaled)
            #pragma unroll
            for (int nt = 0; nt < 16; nt++) {
                S[nt][0] *= scale; S[nt][1] *= scale;
                S[nt][2] *= scale; S[nt][3] *= scale;
            }
            // ---- online softmax ------------------------------------------
            float vA = -INFINITY, vB = -INFINITY;
            #pragma unroll
            for (int nt = 0; nt < 16; nt++) {
                vA = fmaxf(vA, fmaxf(S[nt][0], S[nt][1]));
                vB = fmaxf(vB, fmaxf(S[nt][2], S[nt][3]));
            }
            vA = fmaxf(vA, __shfl_xor_sync(0xffffffffu, vA, 1));
            vA = fmaxf(vA, __shfl_xor_sync(0xffffffffu, vA, 2));
            vB = fmaxf(vB, __shfl_xor_sync(0xffffffffu, vB, 1));
            vB = fmaxf(vB, __shfl_xor_sync(0xffffffffu, vB, 2));
            float mnA = fmaxf(mst[mt][0], vA), mnB = fmaxf(mst[mt][1], vB);
            float fA = __expf(mst[mt][0] - mnA), fB = __expf(mst[mt][1] - mnB);
            mst[mt][0] = mnA; mst[mt][1] = mnB;
            float sA = 0.f, sB = 0.f;
            #pragma unroll
            for (int nt = 0; nt < 16; nt++) {
                S[nt][0] = __expf(S[nt][0] - mnA);
                S[nt][1] = __expf(S[nt][1] - mnA);
                S[nt][2] = __expf(S[nt][2] - mnB);
                S[nt][3] = __expf(S[nt][3] - mnB);
                sA += S[nt][0] + S[nt][1];
                sB += S[nt][2] + S[nt][3];
            }
            sA += __shfl_xor_sync(0xffffffffu, sA, 1);
            sA += __shfl_xor_sync(0xffffffffu, sA, 2);
            sB += __shfl_xor_sync(0xffffffffu, sB, 1);
            sB += __shfl_xor_sync(0xffffffffu, sB, 2);
            lst[mt][0] = lst[mt][0] * fA + sA;
            lst[mt][1] = lst[mt][1] * fB + sB;
            #pragma unroll
            for (int nt = 0; nt < 4; nt++) {
                O[mt][nt][0] *= fA; O[mt][nt][1] *= fA;
                O[mt][nt][2] *= fB; O[mt][nt][3] *= fB;
            }
            // ---- P @ V, single fp16 term ----------------------------------
            #pragma unroll
            for (int kt = 0; kt < 8; kt++) {
                uint32_t ph[4];
                ph[0] = packh2(S[2*kt][0],   S[2*kt][1]);
                ph[1] = packh2(S[2*kt][2],   S[2*kt][3]);
                ph[2] = packh2(S[2*kt+1][0], S[2*kt+1][1]);
                ph[3] = packh2(S[2*kt+1][2], S[2*kt+1][3]);
                uint32_t vrow = kt * 16 + (lane & 15);
                uint32_t bv0[4], bv1[4];
                ldsm_x4_t(bv0, smb + SM_V + vrow * AROW + (lane >> 4) * 16);
                ldsm_x4_t(bv1, smb + SM_V + vrow * AROW + 32 + (lane >> 4) * 16);
                mma16816h(O[mt][0], ph, bv0); mma16816h(O[mt][1], ph, bv0 + 2);
                mma16816h(O[mt][2], ph, bv1); mma16816h(O[mt][3], ph, bv1 + 2);
            }
        }
    }

    // ---- epilogue: normalize, write fp16 ctx directly (out-proj A op) ----
    int r = lane >> 2, c = (lane & 3) * 2;
    #pragma unroll
    for (int mt = 0; mt < 2; mt++) {
        float invA = 1.f / lst[mt][0];
        float invB = 1.f / lst[mt][1];
        int qA = wid * 32 + mt * 16 + r;
        int qB = qA + 8;
        #pragma unroll
        for (int nt = 0; nt < 4; nt++) {
            if (qA < LQ) {
                long ci = ((long)e * MQ + qA * BB + b) * D + h * HD + nt * 8 + c;
                *(uint32_t*)(g_Ac + ci) = packh2(O[mt][nt][0] * invA,
                                                 O[mt][nt][1] * invA);
            }
            if (qB < LQ) {
                long ci = ((long)e * MQ + qB * BB + b) * D + h * HD + nt * 8 + c;
                *(uint32_t*)(g_Ac + ci) = packh2(O[mt][nt][2] * invB,
                                                 O[mt][nt][3] * invB);
            }
        }
    }
}

// ---------------- gated combine + residual + LayerNorm ---------------------
__global__ void __launch_bounds__(256)
combine_ln(const float* __restrict__ tgt,
           const float* __restrict__ gamma,
           const float* __restrict__ beta,
           float* __restrict__ out) {
    int m = blockIdx.x;
    int k = threadIdx.x;
    float g[NE];
    #pragma unroll
    for (int e = 0; e < NE; e++) g[e] = g_gate[m*NE + e];
    float x = tgt[(long)m * D + k];
    #pragma unroll
    for (int e = 0; e < NE; e++)
        x = fmaf(g[e], g_out[(long)e * MQ * D + (long)m * D + k], x);

    __shared__ float red[16];
    float s = x, s2 = x * x;
    #pragma unroll
    for (int o = 16; o > 0; o >>= 1) {
        s  += __shfl_xor_sync(0xffffffffu, s, o);
        s2 += __shfl_xor_sync(0xffffffffu, s2, o);
    }
    int wid = k >> 5, lane = k & 31;
    if (lane == 0) { red[wid] = s; red[8 + wid] = s2; }
    __syncthreads();
    if (k < 32) {
        float a  = (k < 8) ? red[k]     : 0.f;
        float b2 = (k < 8) ? red[8 + k] : 0.f;
        #pragma unroll
        for (int o = 4; o > 0; o >>= 1) {
            a  += __shfl_xor_sync(0xffffffffu, a,  o);
            b2 += __shfl_xor_sync(0xffffffffu, b2, o);
        }
        if (k == 0) { red[0] = a; red[1] = b2; }
    }
    __syncthreads();
    float mu  = red[0] * (1.f / D);
    float var = red[1] * (1.f / D) - mu * mu;
    float r = rsqrtf(var + 1e-5f);
    out[(long)m * D + k] = (x - mu) * r * gamma[k] + beta[k];
}

// ---------------- launch ----------------------------------------------------
extern "C" void kernel_launch(void* const* d_in, const int* in_sizes, int n_in,
                              void* d_out, int out_size) {
    const float* tgt    = (const float*)d_in[0];
    const float* memory = (const float*)d_in[1];
    const float* qpos   = (const float*)d_in[2];
    const float* pos    = (const float*)d_in[3];
    const float* w_in   = (const float*)d_in[4];
    const float* b_in   = (const float*)d_in[5];
    const float* w_out  = (const float*)d_in[6];
    const float* b_out  = (const float*)d_in[7];
    const float* w_gate = (const float*)d_in[8];
    const float* b_gate = (const float*)d_in[9];
    const float* gamma  = (const float*)d_in[10];
    const float* beta   = (const float*)d_in[11];

    float *pOut;
    __half *pQh, *pKVh, *pAq, *pAkv, *pAc, *pWq, *pWkv, *pWo;
    cudaGetSymbolAddress((void**)&pOut, g_out);
    cudaGetSymbolAddress((void**)&pQh,  g_Qh);
    cudaGetSymbolAddress((void**)&pKVh, g_KVh);
    cudaGetSymbolAddress((void**)&pAq,  g_Aq);
    cudaGetSymbolAddress((void**)&pAkv, g_Akv);
    cudaGetSymbolAddress((void**)&pAc,  g_Ac);
    cudaGetSymbolAddress((void**)&pWq,  g_Wq);
    cudaGetSymbolAddress((void**)&pWkv, g_Wkv);
    cudaGetSymbolAddress((void**)&pWo,  g_Wo);

    // one-time resource setup (streams/events; no device memory)
    static cudaStream_t s1 = nullptr;
    static cudaEvent_t evFork = nullptr, evW = nullptr, evS1 = nullptr;
    if (s1 == nullptr) {
        cudaStreamCreateWithFlags(&s1, cudaStreamNonBlocking);
        cudaEventCreateWithFlags(&evFork, cudaEventDisableTiming);
        cudaEventCreateWithFlags(&evW,    cudaEventDisableTiming);
        cudaEventCreateWithFlags(&evS1,   cudaEventDisableTiming);
        cudaFuncSetAttribute(gemm_mma<0>, cudaFuncAttributeMaxDynamicSharedMemorySize, GEMM_SMEM);
        cudaFuncSetAttribute(gemm_mma<1>, cudaFuncAttributeMaxDynamicSharedMemorySize, GEMM_SMEM);
        cudaFuncSetAttribute(attn_mma, cudaFuncAttributeMaxDynamicSharedMemorySize, ATT_SMEM);
    }

    // fork side stream
    cudaEventRecord(evFork, 0);
    cudaStreamWaitEvent(s1, evFork, 0);

    // s1: weight conversions -> Q chain -> gate
    convert_w_all<<<(NEXP*64 + 255)/256, 256, 0, s1>>>(
        w_in, w_out, pWq, pWkv, pWkv + (long)NEXP*KW, pWo);
    cudaEventRecord(evW, s1);
    convert_act<<<(MQ*64 + 255)/256, 256, 0, s1>>>(tgt, qpos, pAq, MQ);
    gemm_mma<1><<<dim3(13, 10, 1), 128, GEMM_SMEM, s1>>>(
        pAq, pWq, b_in, pQh, MQ, NEXP, 0, 0, 0, 0, 768, 0);
    gate_kernel<<<(MQ*32 + 127)/128, 128, 0, s1>>>(tgt, w_gate, b_gate);
    cudaEventRecord(evS1, s1);

    // s0 (default): K/V chain
    convert_kv<<<(MK*64 + 255)/256, 256>>>(memory, pos, pAkv, pAkv + (long)MK*KA);
    cudaStreamWaitEvent(0, evW, 0);
    gemm_mma<1><<<dim3(128, 10, 2), 128, GEMM_SMEM>>>(
        pAkv, pWkv, b_in, pKVh, MK, NEXP,
        (long)MK*KA, (long)NEXP*KW, 256, (long)MK*NEXP, 768, 256);

    // join, then attention -> out projection -> LN
    cudaStreamWaitEvent(0, evS1, 0);
    attn_mma<<<dim3(NH, BB, NE), 128, ATT_SMEM>>>();
    gemm_mma<0><<<dim3(13, 2, 5), 128, GEMM_SMEM>>>(
        pAc, pWo, b_out, pOut, MQ, D,
        (long)MQ*KA, (long)D*KW, D, (long)MQ*D, 0, 0);
    combine_ln<<<MQ, 256>>>(tgt, gamma, beta, (float*)d_out);
}